// round 10
// baseline (speedup 1.0000x reference)
#include <cuda_runtime.h>
#include <cuda_bf16.h>
#include <cstdint>

#define DIM   2048
#define BATCH 32768
#define RCAP1 8192
#define RCAP2 256
#define NSTG  6              // cp.async pipeline depth

// ---------------------------------------------------------------------------
// Device-global scratch
// ---------------------------------------------------------------------------
__device__ __align__(16) float g_H[(size_t)BATCH * DIM];
__device__ __align__(16) float g_logits[BATCH * 2];
__device__ __align__(16) __nv_bfloat16 g_xs[2][(size_t)BATCH * DIM];
__device__ __align__(16) __nv_bfloat16 g_ws[2][(size_t)DIM * DIM];
__device__ __align__(16) float g_Hr[(size_t)RCAP2 * DIM];
__device__ int g_idx[2][BATCH];
__device__ int g_cnt[2];
__device__ int g_rlist1[RCAP1];
__device__ int g_rcnt1[1];
__device__ int g_rlist2[RCAP2];
__device__ int g_rcnt2[1];

// ---------------------------------------------------------------------------
// helpers
// ---------------------------------------------------------------------------
__device__ __forceinline__ uint32_t smem_u32_of(const void* p) {
    uint32_t a;
    asm("{ .reg .u64 t; cvta.to.shared.u64 t, %1; cvt.u32.u64 %0, t; }" : "=r"(a) : "l"(p));
    return a;
}
__device__ __forceinline__ void cp16(uint32_t dst, const void* src) {
    asm volatile("cp.async.cg.shared.global [%0], [%1], 16;" :: "r"(dst), "l"(src));
}
__device__ __forceinline__ void ldsm_x4(uint32_t* r, uint32_t addr) {
    asm volatile("ldmatrix.sync.aligned.m8n8.x4.shared.b16 {%0,%1,%2,%3}, [%4];"
                 : "=r"(r[0]), "=r"(r[1]), "=r"(r[2]), "=r"(r[3]) : "r"(addr));
}
__device__ __forceinline__ void mma16816(float* c, const uint32_t* a,
                                         uint32_t b0, uint32_t b1) {
    asm volatile("mma.sync.aligned.m16n8k16.row.col.f32.bf16.bf16.f32 "
                 "{%0,%1,%2,%3}, {%4,%5,%6,%7}, {%8,%9}, {%0,%1,%2,%3};"
                 : "+f"(c[0]), "+f"(c[1]), "+f"(c[2]), "+f"(c[3])
                 : "r"(a[0]), "r"(a[1]), "r"(a[2]), "r"(a[3]), "r"(b0), "r"(b1));
}
__device__ __forceinline__ uint32_t swz(uint32_t off) {       // Swizzle<3,4,3>
    return off ^ (((off >> 7) & 7u) << 4);
}

// ---------------------------------------------------------------------------
// Split-bf16 GEMM via mma.sync:  C[m,n] = sum_k A[m,k]*W[n,k] + bias[n]
// NPROD products x 64 k-tiles (BK=32). CTA tile 128x128, 4 warps
// (warp tile 64x64, 2m x 2n), NSTG-stage cp.async, 2 CTAs/SM.
// ldsm redundancy 2x (vs 4x at 8 warps) -> tensor-bound, not crossbar-bound.
// ---------------------------------------------------------------------------
template<int NPROD, bool GATHER>
__global__ __launch_bounds__(128)
void gemm_mma(const __nv_bfloat16* __restrict__ Ah, const __nv_bfloat16* __restrict__ Am,
              const __nv_bfloat16* __restrict__ Bh, const __nv_bfloat16* __restrict__ Bm,
              const float* __restrict__ bias, float* __restrict__ C,
              const int* __restrict__ idx, const int* __restrict__ cnt_p)
{
    constexpr int KT    = DIM / 32;
    constexpr int T     = NPROD * KT;
    constexpr int STAGE = 16384;

    extern __shared__ __align__(128) char smem[];
    __shared__ int sidx[128];
    const uint32_t sbase = smem_u32_of(smem);

    const int tid = threadIdx.x;
    const int wid = tid >> 5, lid = tid & 31;
    const int wm  = wid >> 1;                 // 0..1
    const int wn  = wid & 1;                  // 0..1
    const int m0  = blockIdx.y * 128;
    const int n0  = blockIdx.x * 128;

    if (GATHER) {
        const int cnt = __ldg(cnt_p);
        if (m0 >= cnt) return;
        sidx[tid] = __ldg(&idx[min(m0 + tid, cnt - 1)]);
        __syncthreads();
    }

    const int PA[3] = {0, 0, 1};
    const int PB[3] = {0, 1, 0};
    const __nv_bfloat16* Abase[2] = {Ah, Am};
    const __nv_bfloat16* Bbase[2] = {Bh, Bm};

    const int lrow = tid >> 1;          // 0..63
    const int ce   = (tid & 1) * 16;    // element offset within k-tile (0 or 16)

    const int ar0 = GATHER ? sidx[lrow]      : (m0 + lrow);
    const int ar1 = GATHER ? sidx[lrow + 64] : (m0 + lrow + 64);
    const size_t aoff0 = (size_t)ar0 * DIM;
    const size_t aoff1 = (size_t)ar1 * DIM;
    const size_t boff0 = (size_t)(n0 + lrow) * DIM;
    const size_t boff1 = (size_t)(n0 + lrow + 64) * DIM;

    auto load_stage = [&](int t, int buf) {
        const int p  = t / KT;
        const int kt = t % KT;
        const size_t kofs = (size_t)kt * 32 + ce;
        const __nv_bfloat16* As = Abase[PA[p]];
        const __nv_bfloat16* Bs = Bbase[PB[p]];
        const uint32_t sa = sbase + buf * STAGE;
        const uint32_t sb = sa + 8192;
        const uint32_t c2 = (uint32_t)ce * 2;
        cp16(sa + swz((uint32_t)lrow * 64 + c2),             As + aoff0 + kofs);
        cp16(sa + swz((uint32_t)lrow * 64 + c2 + 16),        As + aoff0 + kofs + 8);
        cp16(sa + swz((uint32_t)(lrow + 64) * 64 + c2),      As + aoff1 + kofs);
        cp16(sa + swz((uint32_t)(lrow + 64) * 64 + c2 + 16), As + aoff1 + kofs + 8);
        cp16(sb + swz((uint32_t)lrow * 64 + c2),             Bs + boff0 + kofs);
        cp16(sb + swz((uint32_t)lrow * 64 + c2 + 16),        Bs + boff0 + kofs + 8);
        cp16(sb + swz((uint32_t)(lrow + 64) * 64 + c2),      Bs + boff1 + kofs);
        cp16(sb + swz((uint32_t)(lrow + 64) * 64 + c2 + 16), Bs + boff1 + kofs + 8);
        asm volatile("cp.async.commit_group;" ::: "memory");
    };

    float acc[4][8][4];
#pragma unroll
    for (int i = 0; i < 4; i++)
#pragma unroll
        for (int j = 0; j < 8; j++)
#pragma unroll
            for (int r = 0; r < 4; r++) acc[i][j][r] = 0.f;

    const uint32_t a_row = wm * 64 + (lid & 7) + ((lid >> 3) & 1) * 8;
    const uint32_t a_kb  = ((lid >> 4) & 1) * 16;
    const uint32_t b_row = wn * 64 + (lid & 7) + ((lid >> 4) & 1) * 8;
    const uint32_t b_kb  = ((lid >> 3) & 1) * 16;

#pragma unroll
    for (int s = 0; s < NSTG - 1; s++) load_stage(s, s);

    int buf = 0, nbuf = NSTG - 1;
    for (int t = 0; t < T; t++) {
        asm volatile("cp.async.wait_group %0;" :: "n"(NSTG - 2) : "memory");
        __syncthreads();

        const uint32_t sa = sbase + buf * STAGE;
        const uint32_t sb = sa + 8192;

#pragma unroll
        for (int ks = 0; ks < 2; ks++) {
            uint32_t af[4][4], bf[4][4];
#pragma unroll
            for (int mf = 0; mf < 4; mf++)
                ldsm_x4(af[mf], sa + swz((a_row + mf * 16) * 64 + ks * 32 + a_kb));
#pragma unroll
            for (int ng = 0; ng < 4; ng++)
                ldsm_x4(bf[ng], sb + swz((b_row + ng * 16) * 64 + ks * 32 + b_kb));
#pragma unroll
            for (int mf = 0; mf < 4; mf++)
#pragma unroll
                for (int nf = 0; nf < 8; nf++)
                    mma16816(acc[mf][nf], af[mf],
                             bf[nf >> 1][(nf & 1) * 2], bf[nf >> 1][(nf & 1) * 2 + 1]);
        }

        if (t + NSTG - 1 < T) load_stage(t + NSTG - 1, nbuf);
        if (++buf == NSTG) buf = 0;
        if (++nbuf == NSTG) nbuf = 0;
    }

    const int er = lid >> 2;
    const int ec = (lid & 3) * 2;
#pragma unroll
    for (int mf = 0; mf < 4; mf++) {
#pragma unroll
        for (int nf = 0; nf < 8; nf++) {
            const int col = n0 + wn * 64 + nf * 8 + ec;
            const float bx = __ldg(&bias[col]);
            const float by = __ldg(&bias[col + 1]);
            const int r0 = m0 + wm * 64 + mf * 16 + er;
            const int r1 = r0 + 8;
            *(float2*)(C + (size_t)r0 * DIM + col) = make_float2(acc[mf][nf][0] + bx, acc[mf][nf][1] + by);
            *(float2*)(C + (size_t)r1 * DIM + col) = make_float2(acc[mf][nf][2] + bx, acc[mf][nf][3] + by);
        }
    }
}

// ---------------------------------------------------------------------------
// fp32 -> 2-way bf16 split
// ---------------------------------------------------------------------------
__global__ __launch_bounds__(256)
void split2_kernel(const float* __restrict__ in, __nv_bfloat16* __restrict__ h,
                   __nv_bfloat16* __restrict__ m, size_t n)
{
    size_t i = ((size_t)blockIdx.x * 256 + threadIdx.x) * 4;
    if (i >= n) return;
    float4 v = *(const float4*)(in + i);
    float vv[4] = {v.x, v.y, v.z, v.w};
    __nv_bfloat16 hh[4], mm[4];
#pragma unroll
    for (int j = 0; j < 4; j++) {
        float x = vv[j];
        __nv_bfloat16 a = __float2bfloat16(x);
        float r = x - __bfloat162float(a);
        mm[j] = __float2bfloat16(r);
        hh[j] = a;
    }
    *(__nv_bfloat162*)(h + i)     = __nv_bfloat162(hh[0], hh[1]);
    *(__nv_bfloat162*)(h + i + 2) = __nv_bfloat162(hh[2], hh[3]);
    *(__nv_bfloat162*)(m + i)     = __nv_bfloat162(mm[0], mm[1]);
    *(__nv_bfloat162*)(m + i + 2) = __nv_bfloat162(mm[2], mm[3]);
}

// ---------------------------------------------------------------------------
// block reduction of two floats (256 threads)
// ---------------------------------------------------------------------------
__device__ __forceinline__ float2 block_reduce2(float a, float b)
{
    __shared__ float sa[8], sb[8];
    __syncthreads();
    int lane = threadIdx.x & 31, wd = threadIdx.x >> 5;
#pragma unroll
    for (int o = 16; o; o >>= 1) {
        a += __shfl_down_sync(0xFFFFFFFFu, a, o);
        b += __shfl_down_sync(0xFFFFFFFFu, b, o);
    }
    if (lane == 0) { sa[wd] = a; sb[wd] = b; }
    __syncthreads();
    if (wd == 0) {
        a = (lane < 8) ? sa[lane] : 0.f;
        b = (lane < 8) ? sb[lane] : 0.f;
#pragma unroll
        for (int o = 4; o; o >>= 1) {
            a += __shfl_down_sync(0xFFFFFFFFu, a, o);
            b += __shfl_down_sync(0xFFFFFFFFu, b, o);
        }
        if (lane == 0) { sa[0] = a; sb[0] = b; }
    }
    __syncthreads();
    return make_float2(sa[0], sb[0]);
}

// ---------------------------------------------------------------------------
// LN + ReLU + head, 8 rows per block, params in registers, next-row prefetch.
// ---------------------------------------------------------------------------
template<bool SCATTER>
__global__ __launch_bounds__(256)
void ln_head8(const float* __restrict__ H,
              const float* __restrict__ gamma, const float* __restrict__ beta,
              const float* __restrict__ W2, const float* __restrict__ b2,
              const int* __restrict__ idx, const int* __restrict__ cnt_p,
              float* __restrict__ out)
{
    const int base = blockIdx.x * 8;
    int cnt = BATCH;
    if (SCATTER) {
        cnt = __ldg(cnt_p);
        if (base >= cnt) return;
    }
    const int t = threadIdx.x;

    const float4* g4  = (const float4*)gamma;
    const float4* be4 = (const float4*)beta;
    const float4* w04 = (const float4*)W2;
    const float4* w14 = (const float4*)(W2 + DIM);

    const float4 ga = g4[t*2],  gb = g4[t*2+1];
    const float4 ba = be4[t*2], bb = be4[t*2+1];
    const float4 wa = w04[t*2], wb = w04[t*2+1];
    const float4 wc = w14[t*2], wd = w14[t*2+1];
    const float bias0 = __ldg(&b2[0]), bias1 = __ldg(&b2[1]);
    const float inv_d = 1.f / (float)DIM;

    // prefetch row 0
    int rr0 = SCATTER ? min(base, cnt - 1) : base;
    const float4* h4 = (const float4*)(H + (size_t)rr0 * DIM);
    float4 v0 = h4[t*2];
    float4 v1 = h4[t*2+1];

#pragma unroll 1
    for (int r = 0; r < 8; r++) {
        const int row  = base + r;
        const bool act = !SCATTER || (row < cnt);

        float s  = v0.x + v0.y + v0.z + v0.w + v1.x + v1.y + v1.z + v1.w;
        float ss = v0.x*v0.x + v0.y*v0.y + v0.z*v0.z + v0.w*v0.w
                 + v1.x*v1.x + v1.y*v1.y + v1.z*v1.z + v1.w*v1.w;

        // issue next row's loads before the barriers
        float4 n0v, n1v;
        if (r < 7) {
            const int nrow = base + r + 1;
            const int nrr  = SCATTER ? min(nrow, cnt - 1) : nrow;
            const float4* nh4 = (const float4*)(H + (size_t)nrr * DIM);
            n0v = nh4[t*2];
            n1v = nh4[t*2+1];
        }

        float2 red = block_reduce2(s, ss);
        float mu   = red.x * inv_d;
        float var  = red.y * inv_d - mu * mu;
        float rinv = rsqrtf(var + 1e-5f);

        float l0 = 0.f, l1 = 0.f, h;
        h = fmaxf(fmaf((v0.x - mu)*rinv, ga.x, ba.x), 0.f); l0 += h*wa.x; l1 += h*wc.x;
        h = fmaxf(fmaf((v0.y - mu)*rinv, ga.y, ba.y), 0.f); l0 += h*wa.y; l1 += h*wc.y;
        h = fmaxf(fmaf((v0.z - mu)*rinv, ga.z, ba.z), 0.f); l0 += h*wa.z; l1 += h*wc.z;
        h = fmaxf(fmaf((v0.w - mu)*rinv, ga.w, ba.w), 0.f); l0 += h*wa.w; l1 += h*wc.w;
        h = fmaxf(fmaf((v1.x - mu)*rinv, gb.x, bb.x), 0.f); l0 += h*wb.x; l1 += h*wd.x;
        h = fmaxf(fmaf((v1.y - mu)*rinv, gb.y, bb.y), 0.f); l0 += h*wb.y; l1 += h*wd.y;
        h = fmaxf(fmaf((v1.z - mu)*rinv, gb.z, bb.z), 0.f); l0 += h*wb.z; l1 += h*wd.z;
        h = fmaxf(fmaf((v1.w - mu)*rinv, gb.w, bb.w), 0.f); l0 += h*wb.w; l1 += h*wd.w;

        float2 lr = block_reduce2(l0, l1);
        if (t == 0 && act) {
            if (SCATTER) {
                const int o = __ldg(&idx[row]);
                out[o*2]   = lr.x + bias0;
                out[o*2+1] = lr.y + bias1;
            } else {
                out[row*2]   = lr.x + bias0;
                out[row*2+1] = lr.y + bias1;
            }
        }
        v0 = n0v;
        v1 = n1v;
    }
}

// ---------------------------------------------------------------------------
// Flag rows with |l0-l1| < thresh. Single block, ordered compaction.
// ---------------------------------------------------------------------------
__global__ __launch_bounds__(1024)
void flag_scan(const float* __restrict__ L0, float thresh, int cap,
               int* __restrict__ rlist, int* __restrict__ rcnt)
{
    __shared__ int sf[1024];
    const int t = threadIdx.x;
    uint32_t mask = 0;
    int c = 0;
#pragma unroll
    for (int j = 0; j < 32; j++) {
        const int b = t * 32 + j;
        float2 f = ((const float2*)L0)[b];
        const bool fl = fabsf(f.x - f.y) < thresh;
        mask |= (uint32_t)fl << j;
        c += fl;
    }
    sf[t] = c;
    __syncthreads();
    for (int off = 1; off < 1024; off <<= 1) {
        int v = (t >= off) ? sf[t - off] : 0;
        __syncthreads();
        sf[t] += v;
        __syncthreads();
    }
    int pos = sf[t] - c;
#pragma unroll
    for (int j = 0; j < 32; j++) {
        if ((mask >> j) & 1) {
            if (pos < cap) rlist[pos] = t * 32 + j;
            pos++;
        }
    }
    if (t == 1023) rcnt[0] = min(sf[1023], cap);
}

// ---------------------------------------------------------------------------
// Exact fp32 recompute of h = x@W1.T + b1 for flagged rows (column-parallel).
// ---------------------------------------------------------------------------
__global__ __launch_bounds__(256)
void refine_h(const float* __restrict__ x, const float* __restrict__ W1,
              const float* __restrict__ b1,
              const int* __restrict__ rlist, const int* __restrict__ rcnt,
              float* __restrict__ Hr)
{
    const int slot = blockIdx.y;
    if (slot >= __ldg(rcnt)) return;
    const int row = __ldg(&rlist[slot]);

    __shared__ float sx[DIM];
    const int tid = threadIdx.x, wid = tid >> 5, lane = tid & 31;
    for (int i = tid; i < DIM; i += 256) sx[i] = x[(size_t)row * DIM + i];
    __syncthreads();

    const int col0 = blockIdx.x * 64;
#pragma unroll 1
    for (int c = wid; c < 64; c += 8) {
        const int j = col0 + c;
        const float* wr = W1 + (size_t)j * DIM;
        float acc = 0.f;
#pragma unroll 8
        for (int k = lane; k < DIM; k += 32)
            acc = fmaf(sx[k], __ldg(&wr[k]), acc);
#pragma unroll
        for (int o = 16; o; o >>= 1) acc += __shfl_down_sync(0xFFFFFFFFu, acc, o);
        if (lane == 0) Hr[(size_t)slot * DIM + j] = acc + __ldg(&b1[j]);
    }
}

// LN + head from exact h; patch L[row]. One block per slot.
__global__ __launch_bounds__(256)
void refine_fix(const float* __restrict__ Hr,
                const float* __restrict__ gamma, const float* __restrict__ beta,
                const float* __restrict__ W2, const float* __restrict__ b2,
                const int* __restrict__ rlist, const int* __restrict__ rcnt,
                float* __restrict__ L)
{
    const int slot = blockIdx.x;
    if (slot >= __ldg(rcnt)) return;
    const int t = threadIdx.x;
    const float4* h4 = (const float4*)(Hr + (size_t)slot * DIM);
    float4 v0 = h4[t*2];
    float4 v1 = h4[t*2+1];

    float s  = v0.x + v0.y + v0.z + v0.w + v1.x + v1.y + v1.z + v1.w;
    float ss = v0.x*v0.x + v0.y*v0.y + v0.z*v0.z + v0.w*v0.w
             + v1.x*v1.x + v1.y*v1.y + v1.z*v1.z + v1.w*v1.w;
    float2 red = block_reduce2(s, ss);
    const float inv_d = 1.f / (float)DIM;
    float mu = red.x * inv_d, var = red.y * inv_d - mu * mu;
    float rinv = rsqrtf(var + 1e-5f);

    const float4* g4  = (const float4*)gamma;
    const float4* be4 = (const float4*)beta;
    const float4* w04 = (const float4*)W2;
    const float4* w14 = (const float4*)(W2 + DIM);

    float l0 = 0.f, l1 = 0.f;
#pragma unroll
    for (int q = 0; q < 2; q++) {
        float4 v  = q ? v1 : v0;
        float4 g  = g4[t*2+q], be = be4[t*2+q], wa = w04[t*2+q], wbv = w14[t*2+q];
        float h;
        h = fmaxf(fmaf((v.x - mu)*rinv, g.x, be.x), 0.f); l0 += h*wa.x; l1 += h*wbv.x;
        h = fmaxf(fmaf((v.y - mu)*rinv, g.y, be.y), 0.f); l0 += h*wa.y; l1 += h*wbv.y;
        h = fmaxf(fmaf((v.z - mu)*rinv, g.z, be.z), 0.f); l0 += h*wa.z; l1 += h*wbv.z;
        h = fmaxf(fmaf((v.w - mu)*rinv, g.w, be.w), 0.f); l0 += h*wa.w; l1 += h*wbv.w;
    }
    float2 lr = block_reduce2(l0, l1);
    if (t == 0) {
        const int row = __ldg(&rlist[slot]);
        L[row*2]   = lr.x + __ldg(&b2[0]);
        L[row*2+1] = lr.y + __ldg(&b2[1]);
    }
}

// ---------------------------------------------------------------------------
// Deterministic route compaction: 1 block, 1024 threads, 32 rows each.
// ---------------------------------------------------------------------------
__global__ __launch_bounds__(1024)
void route_scan(const float* __restrict__ L0, int* __restrict__ fake_idx,
                int* __restrict__ real_idx, int* __restrict__ cnts)
{
    __shared__ int sf[1024];
    const int t = threadIdx.x;
    uint32_t mask = 0;
    int c = 0;
#pragma unroll
    for (int j = 0; j < 32; j++) {
        const int b = t * 32 + j;
        float2 f = ((const float2*)L0)[b];
        const bool fake = (f.x >= f.y);
        mask |= (uint32_t)fake << j;
        c += fake;
    }
    sf[t] = c;
    __syncthreads();
    for (int off = 1; off < 1024; off <<= 1) {
        int v = (t >= off) ? sf[t - off] : 0;
        __syncthreads();
        sf[t] += v;
        __syncthreads();
    }
    const int total_fake = sf[1023];
    const int excl = sf[t] - c;
    int fpos = excl;
#pragma unroll
    for (int j = 0; j < 32; j++) {
        const int b = t * 32 + j;
        if ((mask >> j) & 1) {
            fake_idx[fpos++] = b;
        } else {
            const int fake_before = excl + __popc(mask & ((1u << j) - 1u));
            real_idx[b - fake_before] = b;
        }
    }
    if (t == 0) { cnts[0] = total_fake; cnts[1] = BATCH - total_fake; }
}

// ---------------------------------------------------------------------------
extern "C" void kernel_launch(void* const* d_in, const int* in_sizes, int n_in,
                              void* d_out, int out_size)
{
    (void)in_sizes; (void)n_in; (void)out_size;
    const float* x = (const float*)d_in[0];

    float *H = nullptr, *L = nullptr, *Hr = nullptr;
    __nv_bfloat16 *xs = nullptr, *ws = nullptr;
    int *idx = nullptr, *cnt = nullptr;
    int *rl1 = nullptr, *rc1 = nullptr, *rl2 = nullptr, *rc2 = nullptr;
    cudaGetSymbolAddress((void**)&H,   g_H);
    cudaGetSymbolAddress((void**)&L,   g_logits);
    cudaGetSymbolAddress((void**)&Hr,  g_Hr);
    cudaGetSymbolAddress((void**)&xs,  g_xs);
    cudaGetSymbolAddress((void**)&ws,  g_ws);
    cudaGetSymbolAddress((void**)&idx, g_idx);
    cudaGetSymbolAddress((void**)&cnt, g_cnt);
    cudaGetSymbolAddress((void**)&rl1, g_rlist1);
    cudaGetSymbolAddress((void**)&rc1, g_rcnt1);
    cudaGetSymbolAddress((void**)&rl2, g_rlist2);
    cudaGetSymbolAddress((void**)&rc2, g_rcnt2);

    const size_t XN = (size_t)BATCH * DIM;
    const size_t WN = (size_t)DIM * DIM;
    __nv_bfloat16 *xh = xs, *xm = xs + XN;
    __nv_bfloat16 *wh = ws, *wm = ws + WN;

    constexpr int SMEM_BYTES = NSTG * 16384;   // 96 KB
    cudaFuncSetAttribute(gemm_mma<2,false>, cudaFuncAttributeMaxDynamicSharedMemorySize, SMEM_BYTES);
    cudaFuncSetAttribute(gemm_mma<3,true>,  cudaFuncAttributeMaxDynamicSharedMemorySize, SMEM_BYTES);

    split2_kernel<<<(int)(XN / 4 / 256), 256>>>(x, xh, xm, XN);

    dim3 grid(DIM / 128, BATCH / 128);        // (16, 256)
    dim3 grid_t1(DIM / 128, RCAP1 / 128);     // (16, 64)

    // ---- first (routing) branch: 2-product GEMM + tiered refine ----
    {
        const float* W1 = (const float*)d_in[1];
        const float* b1 = (const float*)d_in[2];
        const float* lg = (const float*)d_in[3];
        const float* lb = (const float*)d_in[4];
        const float* W2 = (const float*)d_in[5];
        const float* b2 = (const float*)d_in[6];
        split2_kernel<<<(int)(WN / 4 / 256), 256>>>(W1, wh, wm, WN);

        gemm_mma<2,false><<<grid, 128, SMEM_BYTES>>>(xh, xm, wh, wm, b1, H,
                                                     nullptr, nullptr);
        ln_head8<false><<<BATCH / 8, 256>>>(H, lg, lb, W2, b2, nullptr, nullptr, L);

        flag_scan<<<1, 1024>>>(L, 1e-2f, RCAP1, rl1, rc1);
        gemm_mma<3,true><<<grid_t1, 128, SMEM_BYTES>>>(xh, xm, wh, wm, b1, H,
                                                       rl1, rc1);
        ln_head8<true><<<RCAP1 / 8, 256>>>(H, lg, lb, W2, b2, rl1, rc1, L);

        flag_scan<<<1, 1024>>>(L, 1e-3f, RCAP2, rl2, rc2);
        refine_h<<<dim3(32, RCAP2), 256>>>(x, W1, b1, rl2, rc2, Hr);
        refine_fix<<<RCAP2, 256>>>(Hr, lg, lb, W2, b2, rl2, rc2, L);
    }

    route_scan<<<1, 1024>>>(L, idx, idx + BATCH, cnt);

    // ---- fake (route==0) and real branches: only their rows, 3 products ----
    for (int br = 1; br < 3; br++) {
        const float* W1 = (const float*)d_in[1 + br * 6 + 0];
        const float* b1 = (const float*)d_in[1 + br * 6 + 1];
        const float* lg = (const float*)d_in[1 + br * 6 + 2];
        const float* lb = (const float*)d_in[1 + br * 6 + 3];
        const float* W2 = (const float*)d_in[1 + br * 6 + 4];
        const float* b2 = (const float*)d_in[1 + br * 6 + 5];

        split2_kernel<<<(int)(WN / 4 / 256), 256>>>(W1, wh, wm, WN);

        int* bidx = idx + (br - 1) * BATCH;
        int* bcnt = cnt + (br - 1);
        gemm_mma<3,true><<<grid, 128, SMEM_BYTES>>>(xh, xm, wh, wm, b1, H,
                                                    bidx, bcnt);
        ln_head8<true><<<BATCH / 8, 256>>>(H, lg, lb, W2, b2, bidx, bcnt,
                                           (float*)d_out);
    }
}

// round 11
// speedup vs baseline: 1.2423x; 1.2423x over previous
#include <cuda_runtime.h>
#include <cuda_bf16.h>
#include <cstdint>

#define DIM   2048
#define BATCH 32768
#define RCAP1 8192
#define RCAP2 256
#define NSTG  6              // cp.async pipeline depth

// ---------------------------------------------------------------------------
// Device-global scratch
// ---------------------------------------------------------------------------
__device__ __align__(16) float g_H[(size_t)BATCH * DIM];
__device__ __align__(16) float g_logits[BATCH * 2];
__device__ __align__(16) __nv_bfloat16 g_xs[2][(size_t)BATCH * DIM];
__device__ __align__(16) __nv_bfloat16 g_ws[2][(size_t)DIM * DIM];
__device__ __align__(16) float g_Hr[(size_t)RCAP2 * DIM];
__device__ int g_idx[2][BATCH];
__device__ int g_cnt[2];
__device__ int g_rlist1[RCAP1];
__device__ int g_rcnt1[1];
__device__ int g_rlist2[RCAP2];
__device__ int g_rcnt2[1];

// ---------------------------------------------------------------------------
// helpers
// ---------------------------------------------------------------------------
__device__ __forceinline__ uint32_t smem_u32_of(const void* p) {
    uint32_t a;
    asm("{ .reg .u64 t; cvta.to.shared.u64 t, %1; cvt.u32.u64 %0, t; }" : "=r"(a) : "l"(p));
    return a;
}
__device__ __forceinline__ void cp16(uint32_t dst, const void* src) {
    asm volatile("cp.async.cg.shared.global [%0], [%1], 16;" :: "r"(dst), "l"(src));
}
__device__ __forceinline__ void ldsm_x4(uint32_t* r, uint32_t addr) {
    asm volatile("ldmatrix.sync.aligned.m8n8.x4.shared.b16 {%0,%1,%2,%3}, [%4];"
                 : "=r"(r[0]), "=r"(r[1]), "=r"(r[2]), "=r"(r[3]) : "r"(addr));
}
__device__ __forceinline__ void mma16816(float* c, const uint32_t* a,
                                         uint32_t b0, uint32_t b1) {
    asm volatile("mma.sync.aligned.m16n8k16.row.col.f32.bf16.bf16.f32 "
                 "{%0,%1,%2,%3}, {%4,%5,%6,%7}, {%8,%9}, {%0,%1,%2,%3};"
                 : "+f"(c[0]), "+f"(c[1]), "+f"(c[2]), "+f"(c[3])
                 : "r"(a[0]), "r"(a[1]), "r"(a[2]), "r"(a[3]), "r"(b0), "r"(b1));
}
__device__ __forceinline__ uint32_t swz(uint32_t off) {       // Swizzle<3,4,3>
    return off ^ (((off >> 7) & 7u) << 4);
}

// ---------------------------------------------------------------------------
// Split-bf16 GEMM via mma.sync (R9-proven config):
// C[m,n] = sum_k A[m,k]*W[n,k] + bias[n]
// NPROD products (2: hh,hm | 3: hh,hm,mh) x 64 k-tiles (BK=32). Tile 128x128,
// 8 warps (warp tile 64x32), NSTG-stage cp.async, 2 CTAs/SM.
// GATHER: A rows taken from idx[] (compacted row list).
// ---------------------------------------------------------------------------
template<int NPROD, bool GATHER>
__global__ __launch_bounds__(256)
void gemm_mma(const __nv_bfloat16* __restrict__ Ah, const __nv_bfloat16* __restrict__ Am,
              const __nv_bfloat16* __restrict__ Bh, const __nv_bfloat16* __restrict__ Bm,
              const float* __restrict__ bias, float* __restrict__ C,
              const int* __restrict__ idx, const int* __restrict__ cnt_p)
{
    constexpr int KT    = DIM / 32;
    constexpr int T     = NPROD * KT;
    constexpr int STAGE = 16384;

    extern __shared__ __align__(128) char smem[];
    __shared__ int sidx[128];
    const uint32_t sbase = smem_u32_of(smem);

    const int tid = threadIdx.x;
    const int wid = tid >> 5, lid = tid & 31;
    const int wm  = wid >> 2;
    const int wn  = wid & 3;
    const int m0  = blockIdx.y * 128;
    const int n0  = blockIdx.x * 128;

    if (GATHER) {
        const int cnt = __ldg(cnt_p);
        if (m0 >= cnt) return;
        if (tid < 128) sidx[tid] = __ldg(&idx[min(m0 + tid, cnt - 1)]);
        __syncthreads();
    }

    const int PA[3] = {0, 0, 1};
    const int PB[3] = {0, 1, 0};
    const __nv_bfloat16* Abase[2] = {Ah, Am};
    const __nv_bfloat16* Bbase[2] = {Bh, Bm};

    const int lrow = tid >> 2;          // 0..63
    const int lch  = tid & 3;

    const int ar0 = GATHER ? sidx[lrow]      : (m0 + lrow);
    const int ar1 = GATHER ? sidx[lrow + 64] : (m0 + lrow + 64);
    const size_t aoff0 = (size_t)ar0 * DIM;
    const size_t aoff1 = (size_t)ar1 * DIM;
    const size_t boff0 = (size_t)(n0 + lrow) * DIM;
    const size_t boff1 = (size_t)(n0 + lrow + 64) * DIM;

    auto load_stage = [&](int t, int buf) {
        const int p  = t / KT;
        const int kt = t % KT;
        const size_t kofs = (size_t)kt * 32 + lch * 8;
        const __nv_bfloat16* As = Abase[PA[p]];
        const __nv_bfloat16* Bs = Bbase[PB[p]];
        const uint32_t sa = sbase + buf * STAGE;
        const uint32_t sb = sa + 8192;
        cp16(sa + swz((uint32_t)lrow * 64 + lch * 16),        As + aoff0 + kofs);
        cp16(sa + swz((uint32_t)(lrow + 64) * 64 + lch * 16), As + aoff1 + kofs);
        cp16(sb + swz((uint32_t)lrow * 64 + lch * 16),        Bs + boff0 + kofs);
        cp16(sb + swz((uint32_t)(lrow + 64) * 64 + lch * 16), Bs + boff1 + kofs);
        asm volatile("cp.async.commit_group;" ::: "memory");
    };

    float acc[4][4][4];
#pragma unroll
    for (int i = 0; i < 4; i++)
#pragma unroll
        for (int j = 0; j < 4; j++)
#pragma unroll
            for (int r = 0; r < 4; r++) acc[i][j][r] = 0.f;

    const uint32_t a_row = wm * 64 + (lid & 7) + ((lid >> 3) & 1) * 8;
    const uint32_t a_kb  = ((lid >> 4) & 1) * 16;
    const uint32_t b_row = wn * 32 + (lid & 7) + ((lid >> 4) & 1) * 8;
    const uint32_t b_kb  = ((lid >> 3) & 1) * 16;

#pragma unroll
    for (int s = 0; s < NSTG - 1; s++) load_stage(s, s);

    int buf = 0, nbuf = NSTG - 1;
    for (int t = 0; t < T; t++) {
        asm volatile("cp.async.wait_group %0;" :: "n"(NSTG - 2) : "memory");
        __syncthreads();

        const uint32_t sa = sbase + buf * STAGE;
        const uint32_t sb = sa + 8192;

#pragma unroll
        for (int ks = 0; ks < 2; ks++) {
            uint32_t af[4][4], bf[2][4];
#pragma unroll
            for (int mf = 0; mf < 4; mf++)
                ldsm_x4(af[mf], sa + swz((a_row + mf * 16) * 64 + ks * 32 + a_kb));
#pragma unroll
            for (int ng = 0; ng < 2; ng++)
                ldsm_x4(bf[ng], sb + swz((b_row + ng * 16) * 64 + ks * 32 + b_kb));
#pragma unroll
            for (int mf = 0; mf < 4; mf++)
#pragma unroll
                for (int nf = 0; nf < 4; nf++)
                    mma16816(acc[mf][nf], af[mf],
                             bf[nf >> 1][(nf & 1) * 2], bf[nf >> 1][(nf & 1) * 2 + 1]);
        }

        if (t + NSTG - 1 < T) load_stage(t + NSTG - 1, nbuf);
        if (++buf == NSTG) buf = 0;
        if (++nbuf == NSTG) nbuf = 0;
    }

    const int er = lid >> 2;
    const int ec = (lid & 3) * 2;
#pragma unroll
    for (int mf = 0; mf < 4; mf++) {
#pragma unroll
        for (int nf = 0; nf < 4; nf++) {
            const int col = n0 + wn * 32 + nf * 8 + ec;
            const float bx = __ldg(&bias[col]);
            const float by = __ldg(&bias[col + 1]);
            const int r0 = m0 + wm * 64 + mf * 16 + er;
            const int r1 = r0 + 8;
            *(float2*)(C + (size_t)r0 * DIM + col) = make_float2(acc[mf][nf][0] + bx, acc[mf][nf][1] + by);
            *(float2*)(C + (size_t)r1 * DIM + col) = make_float2(acc[mf][nf][2] + bx, acc[mf][nf][3] + by);
        }
    }
}

// ---------------------------------------------------------------------------
// fp32 -> 2-way bf16 split
// ---------------------------------------------------------------------------
__global__ __launch_bounds__(256)
void split2_kernel(const float* __restrict__ in, __nv_bfloat16* __restrict__ h,
                   __nv_bfloat16* __restrict__ m, size_t n)
{
    size_t i = ((size_t)blockIdx.x * 256 + threadIdx.x) * 4;
    if (i >= n) return;
    float4 v = *(const float4*)(in + i);
    float vv[4] = {v.x, v.y, v.z, v.w};
    __nv_bfloat16 hh[4], mm[4];
#pragma unroll
    for (int j = 0; j < 4; j++) {
        float x = vv[j];
        __nv_bfloat16 a = __float2bfloat16(x);
        float r = x - __bfloat162float(a);
        mm[j] = __float2bfloat16(r);
        hh[j] = a;
    }
    *(__nv_bfloat162*)(h + i)     = __nv_bfloat162(hh[0], hh[1]);
    *(__nv_bfloat162*)(h + i + 2) = __nv_bfloat162(hh[2], hh[3]);
    *(__nv_bfloat162*)(m + i)     = __nv_bfloat162(mm[0], mm[1]);
    *(__nv_bfloat162*)(m + i + 2) = __nv_bfloat162(mm[2], mm[3]);
}

// ---------------------------------------------------------------------------
// block reduction of two floats (256 threads)
// ---------------------------------------------------------------------------
__device__ __forceinline__ float2 block_reduce2(float a, float b)
{
    __shared__ float sa[8], sb[8];
    __syncthreads();
    int lane = threadIdx.x & 31, wd = threadIdx.x >> 5;
#pragma unroll
    for (int o = 16; o; o >>= 1) {
        a += __shfl_down_sync(0xFFFFFFFFu, a, o);
        b += __shfl_down_sync(0xFFFFFFFFu, b, o);
    }
    if (lane == 0) { sa[wd] = a; sb[wd] = b; }
    __syncthreads();
    if (wd == 0) {
        a = (lane < 8) ? sa[lane] : 0.f;
        b = (lane < 8) ? sb[lane] : 0.f;
#pragma unroll
        for (int o = 4; o; o >>= 1) {
            a += __shfl_down_sync(0xFFFFFFFFu, a, o);
            b += __shfl_down_sync(0xFFFFFFFFu, b, o);
        }
        if (lane == 0) { sa[0] = a; sb[0] = b; }
    }
    __syncthreads();
    return make_float2(sa[0], sb[0]);
}

// ---------------------------------------------------------------------------
// LN + ReLU + head, 8 rows per block, params in registers, next-row prefetch.
// ---------------------------------------------------------------------------
template<bool SCATTER>
__global__ __launch_bounds__(256)
void ln_head8(const float* __restrict__ H,
              const float* __restrict__ gamma, const float* __restrict__ beta,
              const float* __restrict__ W2, const float* __restrict__ b2,
              const int* __restrict__ idx, const int* __restrict__ cnt_p,
              float* __restrict__ out)
{
    const int base = blockIdx.x * 8;
    int cnt = BATCH;
    if (SCATTER) {
        cnt = __ldg(cnt_p);
        if (base >= cnt) return;
    }
    const int t = threadIdx.x;

    const float4* g4  = (const float4*)gamma;
    const float4* be4 = (const float4*)beta;
    const float4* w04 = (const float4*)W2;
    const float4* w14 = (const float4*)(W2 + DIM);

    const float4 ga = g4[t*2],  gb = g4[t*2+1];
    const float4 ba = be4[t*2], bb = be4[t*2+1];
    const float4 wa = w04[t*2], wb = w04[t*2+1];
    const float4 wc = w14[t*2], wd = w14[t*2+1];
    const float bias0 = __ldg(&b2[0]), bias1 = __ldg(&b2[1]);
    const float inv_d = 1.f / (float)DIM;

    // prefetch row 0
    int rr0 = SCATTER ? min(base, cnt - 1) : base;
    const float4* h4 = (const float4*)(H + (size_t)rr0 * DIM);
    float4 v0 = h4[t*2];
    float4 v1 = h4[t*2+1];

#pragma unroll 1
    for (int r = 0; r < 8; r++) {
        const int row  = base + r;
        const bool act = !SCATTER || (row < cnt);

        float s  = v0.x + v0.y + v0.z + v0.w + v1.x + v1.y + v1.z + v1.w;
        float ss = v0.x*v0.x + v0.y*v0.y + v0.z*v0.z + v0.w*v0.w
                 + v1.x*v1.x + v1.y*v1.y + v1.z*v1.z + v1.w*v1.w;

        // issue next row's loads before the barriers
        float4 n0v, n1v;
        if (r < 7) {
            const int nrow = base + r + 1;
            const int nrr  = SCATTER ? min(nrow, cnt - 1) : nrow;
            const float4* nh4 = (const float4*)(H + (size_t)nrr * DIM);
            n0v = nh4[t*2];
            n1v = nh4[t*2+1];
        }

        float2 red = block_reduce2(s, ss);
        float mu   = red.x * inv_d;
        float var  = red.y * inv_d - mu * mu;
        float rinv = rsqrtf(var + 1e-5f);

        float l0 = 0.f, l1 = 0.f, h;
        h = fmaxf(fmaf((v0.x - mu)*rinv, ga.x, ba.x), 0.f); l0 += h*wa.x; l1 += h*wc.x;
        h = fmaxf(fmaf((v0.y - mu)*rinv, ga.y, ba.y), 0.f); l0 += h*wa.y; l1 += h*wc.y;
        h = fmaxf(fmaf((v0.z - mu)*rinv, ga.z, ba.z), 0.f); l0 += h*wa.z; l1 += h*wc.z;
        h = fmaxf(fmaf((v0.w - mu)*rinv, ga.w, ba.w), 0.f); l0 += h*wa.w; l1 += h*wc.w;
        h = fmaxf(fmaf((v1.x - mu)*rinv, gb.x, bb.x), 0.f); l0 += h*wb.x; l1 += h*wd.x;
        h = fmaxf(fmaf((v1.y - mu)*rinv, gb.y, bb.y), 0.f); l0 += h*wb.y; l1 += h*wd.y;
        h = fmaxf(fmaf((v1.z - mu)*rinv, gb.z, bb.z), 0.f); l0 += h*wb.z; l1 += h*wd.z;
        h = fmaxf(fmaf((v1.w - mu)*rinv, gb.w, bb.w), 0.f); l0 += h*wb.w; l1 += h*wd.w;

        float2 lr = block_reduce2(l0, l1);
        if (t == 0 && act) {
            if (SCATTER) {
                const int o = __ldg(&idx[row]);
                out[o*2]   = lr.x + bias0;
                out[o*2+1] = lr.y + bias1;
            } else {
                out[row*2]   = lr.x + bias0;
                out[row*2+1] = lr.y + bias1;
            }
        }
        v0 = n0v;
        v1 = n1v;
    }
}

// ---------------------------------------------------------------------------
// Flag rows with |l0-l1| < thresh. Single block, ordered compaction.
// ---------------------------------------------------------------------------
__global__ __launch_bounds__(1024)
void flag_scan(const float* __restrict__ L0, float thresh, int cap,
               int* __restrict__ rlist, int* __restrict__ rcnt)
{
    __shared__ int sf[1024];
    const int t = threadIdx.x;
    uint32_t mask = 0;
    int c = 0;
#pragma unroll
    for (int j = 0; j < 32; j++) {
        const int b = t * 32 + j;
        float2 f = ((const float2*)L0)[b];
        const bool fl = fabsf(f.x - f.y) < thresh;
        mask |= (uint32_t)fl << j;
        c += fl;
    }
    sf[t] = c;
    __syncthreads();
    for (int off = 1; off < 1024; off <<= 1) {
        int v = (t >= off) ? sf[t - off] : 0;
        __syncthreads();
        sf[t] += v;
        __syncthreads();
    }
    int pos = sf[t] - c;
#pragma unroll
    for (int j = 0; j < 32; j++) {
        if ((mask >> j) & 1) {
            if (pos < cap) rlist[pos] = t * 32 + j;
            pos++;
        }
    }
    if (t == 1023) rcnt[0] = min(sf[1023], cap);
}

// ---------------------------------------------------------------------------
// Exact fp32 recompute of h = x@W1.T + b1 for flagged rows (column-parallel).
// ---------------------------------------------------------------------------
__global__ __launch_bounds__(256)
void refine_h(const float* __restrict__ x, const float* __restrict__ W1,
              const float* __restrict__ b1,
              const int* __restrict__ rlist, const int* __restrict__ rcnt,
              float* __restrict__ Hr)
{
    const int slot = blockIdx.y;
    if (slot >= __ldg(rcnt)) return;
    const int row = __ldg(&rlist[slot]);

    __shared__ float sx[DIM];
    const int tid = threadIdx.x, wid = tid >> 5, lane = tid & 31;
    for (int i = tid; i < DIM; i += 256) sx[i] = x[(size_t)row * DIM + i];
    __syncthreads();

    const int col0 = blockIdx.x * 64;
#pragma unroll 1
    for (int c = wid; c < 64; c += 8) {
        const int j = col0 + c;
        const float* wr = W1 + (size_t)j * DIM;
        float acc = 0.f;
#pragma unroll 8
        for (int k = lane; k < DIM; k += 32)
            acc = fmaf(sx[k], __ldg(&wr[k]), acc);
#pragma unroll
        for (int o = 16; o; o >>= 1) acc += __shfl_down_sync(0xFFFFFFFFu, acc, o);
        if (lane == 0) Hr[(size_t)slot * DIM + j] = acc + __ldg(&b1[j]);
    }
}

// LN + head from exact h; patch L[row]. One block per slot.
__global__ __launch_bounds__(256)
void refine_fix(const float* __restrict__ Hr,
                const float* __restrict__ gamma, const float* __restrict__ beta,
                const float* __restrict__ W2, const float* __restrict__ b2,
                const int* __restrict__ rlist, const int* __restrict__ rcnt,
                float* __restrict__ L)
{
    const int slot = blockIdx.x;
    if (slot >= __ldg(rcnt)) return;
    const int t = threadIdx.x;
    const float4* h4 = (const float4*)(Hr + (size_t)slot * DIM);
    float4 v0 = h4[t*2];
    float4 v1 = h4[t*2+1];

    float s  = v0.x + v0.y + v0.z + v0.w + v1.x + v1.y + v1.z + v1.w;
    float ss = v0.x*v0.x + v0.y*v0.y + v0.z*v0.z + v0.w*v0.w
             + v1.x*v1.x + v1.y*v1.y + v1.z*v1.z + v1.w*v1.w;
    float2 red = block_reduce2(s, ss);
    const float inv_d = 1.f / (float)DIM;
    float mu = red.x * inv_d, var = red.y * inv_d - mu * mu;
    float rinv = rsqrtf(var + 1e-5f);

    const float4* g4  = (const float4*)gamma;
    const float4* be4 = (const float4*)beta;
    const float4* w04 = (const float4*)W2;
    const float4* w14 = (const float4*)(W2 + DIM);

    float l0 = 0.f, l1 = 0.f;
#pragma unroll
    for (int q = 0; q < 2; q++) {
        float4 v  = q ? v1 : v0;
        float4 g  = g4[t*2+q], be = be4[t*2+q], wa = w04[t*2+q], wbv = w14[t*2+q];
        float h;
        h = fmaxf(fmaf((v.x - mu)*rinv, g.x, be.x), 0.f); l0 += h*wa.x; l1 += h*wbv.x;
        h = fmaxf(fmaf((v.y - mu)*rinv, g.y, be.y), 0.f); l0 += h*wa.y; l1 += h*wbv.y;
        h = fmaxf(fmaf((v.z - mu)*rinv, g.z, be.z), 0.f); l0 += h*wa.z; l1 += h*wbv.z;
        h = fmaxf(fmaf((v.w - mu)*rinv, g.w, be.w), 0.f); l0 += h*wa.w; l1 += h*wbv.w;
    }
    float2 lr = block_reduce2(l0, l1);
    if (t == 0) {
        const int row = __ldg(&rlist[slot]);
        L[row*2]   = lr.x + __ldg(&b2[0]);
        L[row*2+1] = lr.y + __ldg(&b2[1]);
    }
}

// ---------------------------------------------------------------------------
// Deterministic route compaction: 1 block, 1024 threads, 32 rows each.
// ---------------------------------------------------------------------------
__global__ __launch_bounds__(1024)
void route_scan(const float* __restrict__ L0, int* __restrict__ fake_idx,
                int* __restrict__ real_idx, int* __restrict__ cnts)
{
    __shared__ int sf[1024];
    const int t = threadIdx.x;
    uint32_t mask = 0;
    int c = 0;
#pragma unroll
    for (int j = 0; j < 32; j++) {
        const int b = t * 32 + j;
        float2 f = ((const float2*)L0)[b];
        const bool fake = (f.x >= f.y);
        mask |= (uint32_t)fake << j;
        c += fake;
    }
    sf[t] = c;
    __syncthreads();
    for (int off = 1; off < 1024; off <<= 1) {
        int v = (t >= off) ? sf[t - off] : 0;
        __syncthreads();
        sf[t] += v;
        __syncthreads();
    }
    const int total_fake = sf[1023];
    const int excl = sf[t] - c;
    int fpos = excl;
#pragma unroll
    for (int j = 0; j < 32; j++) {
        const int b = t * 32 + j;
        if ((mask >> j) & 1) {
            fake_idx[fpos++] = b;
        } else {
            const int fake_before = excl + __popc(mask & ((1u << j) - 1u));
            real_idx[b - fake_before] = b;
        }
    }
    if (t == 0) { cnts[0] = total_fake; cnts[1] = BATCH - total_fake; }
}

// ---------------------------------------------------------------------------
extern "C" void kernel_launch(void* const* d_in, const int* in_sizes, int n_in,
                              void* d_out, int out_size)
{
    (void)in_sizes; (void)n_in; (void)out_size;
    const float* x = (const float*)d_in[0];

    float *H = nullptr, *L = nullptr, *Hr = nullptr;
    __nv_bfloat16 *xs = nullptr, *ws = nullptr;
    int *idx = nullptr, *cnt = nullptr;
    int *rl1 = nullptr, *rc1 = nullptr, *rl2 = nullptr, *rc2 = nullptr;
    cudaGetSymbolAddress((void**)&H,   g_H);
    cudaGetSymbolAddress((void**)&L,   g_logits);
    cudaGetSymbolAddress((void**)&Hr,  g_Hr);
    cudaGetSymbolAddress((void**)&xs,  g_xs);
    cudaGetSymbolAddress((void**)&ws,  g_ws);
    cudaGetSymbolAddress((void**)&idx, g_idx);
    cudaGetSymbolAddress((void**)&cnt, g_cnt);
    cudaGetSymbolAddress((void**)&rl1, g_rlist1);
    cudaGetSymbolAddress((void**)&rc1, g_rcnt1);
    cudaGetSymbolAddress((void**)&rl2, g_rlist2);
    cudaGetSymbolAddress((void**)&rc2, g_rcnt2);

    const size_t XN = (size_t)BATCH * DIM;
    const size_t WN = (size_t)DIM * DIM;
    __nv_bfloat16 *xh = xs, *xm = xs + XN;
    __nv_bfloat16 *wh = ws, *wm = ws + WN;

    constexpr int SMEM_BYTES = NSTG * 16384;   // 96 KB
    cudaFuncSetAttribute(gemm_mma<2,false>, cudaFuncAttributeMaxDynamicSharedMemorySize, SMEM_BYTES);
    cudaFuncSetAttribute(gemm_mma<3,true>,  cudaFuncAttributeMaxDynamicSharedMemorySize, SMEM_BYTES);

    split2_kernel<<<(int)(XN / 4 / 256), 256>>>(x, xh, xm, XN);

    dim3 grid(DIM / 128, BATCH / 128);        // (16, 256)
    dim3 grid_t1(DIM / 128, RCAP1 / 128);     // (16, 64)

    // ---- first (routing) branch: 2-product GEMM + tiered refine ----
    {
        const float* W1 = (const float*)d_in[1];
        const float* b1 = (const float*)d_in[2];
        const float* lg = (const float*)d_in[3];
        const float* lb = (const float*)d_in[4];
        const float* W2 = (const float*)d_in[5];
        const float* b2 = (const float*)d_in[6];
        split2_kernel<<<(int)(WN / 4 / 256), 256>>>(W1, wh, wm, WN);

        gemm_mma<2,false><<<grid, 256, SMEM_BYTES>>>(xh, xm, wh, wm, b1, H,
                                                     nullptr, nullptr);
        ln_head8<false><<<BATCH / 8, 256>>>(H, lg, lb, W2, b2, nullptr, nullptr, L);

        flag_scan<<<1, 1024>>>(L, 1e-2f, RCAP1, rl1, rc1);
        gemm_mma<3,true><<<grid_t1, 256, SMEM_BYTES>>>(xh, xm, wh, wm, b1, H,
                                                       rl1, rc1);
        ln_head8<true><<<RCAP1 / 8, 256>>>(H, lg, lb, W2, b2, rl1, rc1, L);

        flag_scan<<<1, 1024>>>(L, 1e-3f, RCAP2, rl2, rc2);
        refine_h<<<dim3(32, RCAP2), 256>>>(x, W1, b1, rl2, rc2, Hr);
        refine_fix<<<RCAP2, 256>>>(Hr, lg, lb, W2, b2, rl2, rc2, L);
    }

    route_scan<<<1, 1024>>>(L, idx, idx + BATCH, cnt);

    // ---- fake (route==0) and real branches: only their rows, 3 products ----
    for (int br = 1; br < 3; br++) {
        const float* W1 = (const float*)d_in[1 + br * 6 + 0];
        const float* b1 = (const float*)d_in[1 + br * 6 + 1];
        const float* lg = (const float*)d_in[1 + br * 6 + 2];
        const float* lb = (const float*)d_in[1 + br * 6 + 3];
        const float* W2 = (const float*)d_in[1 + br * 6 + 4];
        const float* b2 = (const float*)d_in[1 + br * 6 + 5];

        split2_kernel<<<(int)(WN / 4 / 256), 256>>>(W1, wh, wm, WN);

        int* bidx = idx + (br - 1) * BATCH;
        int* bcnt = cnt + (br - 1);
        gemm_mma<3,true><<<grid, 256, SMEM_BYTES>>>(xh, xm, wh, wm, b1, H,
                                                    bidx, bcnt);
        ln_head8<true><<<BATCH / 8, 256>>>(H, lg, lb, W2, b2, bidx, bcnt,
                                           (float*)d_out);
    }
}

// round 12
// speedup vs baseline: 1.4928x; 1.2017x over previous
#include <cuda_runtime.h>
#include <cuda_bf16.h>
#include <cstdint>

#define DIM   2048
#define BATCH 32768
#define RCAP1 8192
#define RCAP2 256
#define NSTG  6              // cp.async pipeline depth

// ---------------------------------------------------------------------------
// Device-global scratch
// ---------------------------------------------------------------------------
__device__ __align__(16) float g_H[(size_t)BATCH * DIM];
__device__ __align__(16) float g_logits[BATCH * 2];
__device__ __align__(16) __nv_bfloat16 g_xs[2][(size_t)BATCH * DIM];
__device__ __align__(16) __nv_bfloat16 g_ws[2][(size_t)DIM * DIM];
__device__ __align__(16) float g_Hr[(size_t)RCAP2 * DIM];
__device__ int g_idx[2][BATCH];
__device__ int g_cnt[2];
__device__ int g_rlist1[RCAP1];
__device__ int g_rcnt1[1];
__device__ int g_rlist2[RCAP2];
__device__ int g_rcnt2[1];

// ---------------------------------------------------------------------------
// helpers
// ---------------------------------------------------------------------------
__device__ __forceinline__ uint32_t smem_u32_of(const void* p) {
    uint32_t a;
    asm("{ .reg .u64 t; cvta.to.shared.u64 t, %1; cvt.u32.u64 %0, t; }" : "=r"(a) : "l"(p));
    return a;
}
__device__ __forceinline__ void cp16(uint32_t dst, const void* src) {
    asm volatile("cp.async.cg.shared.global [%0], [%1], 16;" :: "r"(dst), "l"(src));
}
__device__ __forceinline__ void ldsm_x4(uint32_t* r, uint32_t addr) {
    asm volatile("ldmatrix.sync.aligned.m8n8.x4.shared.b16 {%0,%1,%2,%3}, [%4];"
                 : "=r"(r[0]), "=r"(r[1]), "=r"(r[2]), "=r"(r[3]) : "r"(addr));
}
__device__ __forceinline__ void mma16816(float* c, const uint32_t* a,
                                         uint32_t b0, uint32_t b1) {
    asm volatile("mma.sync.aligned.m16n8k16.row.col.f32.bf16.bf16.f32 "
                 "{%0,%1,%2,%3}, {%4,%5,%6,%7}, {%8,%9}, {%0,%1,%2,%3};"
                 : "+f"(c[0]), "+f"(c[1]), "+f"(c[2]), "+f"(c[3])
                 : "r"(a[0]), "r"(a[1]), "r"(a[2]), "r"(a[3]), "r"(b0), "r"(b1));
}
__device__ __forceinline__ uint32_t swz(uint32_t off) {       // Swizzle<3,4,3>
    return off ^ (((off >> 7) & 7u) << 4);
}

// ---------------------------------------------------------------------------
// Split-bf16 GEMM via mma.sync (R9-proven config):
// C[m,n] = sum_k A[m,k]*W[n,k] + bias[n]
// NPROD products (1: hh | 2: hh,hm | 3: hh,hm,mh) x 64 k-tiles (BK=32).
// Tile 128x128, 8 warps (warp tile 64x32), NSTG-stage cp.async, 2 CTAs/SM.
// GATHER: A rows taken from idx[] (compacted row list).
// ---------------------------------------------------------------------------
template<int NPROD, bool GATHER>
__global__ __launch_bounds__(256)
void gemm_mma(const __nv_bfloat16* __restrict__ Ah, const __nv_bfloat16* __restrict__ Am,
              const __nv_bfloat16* __restrict__ Bh, const __nv_bfloat16* __restrict__ Bm,
              const float* __restrict__ bias, float* __restrict__ C,
              const int* __restrict__ idx, const int* __restrict__ cnt_p)
{
    constexpr int KT    = DIM / 32;
    constexpr int T     = NPROD * KT;
    constexpr int STAGE = 16384;

    extern __shared__ __align__(128) char smem[];
    __shared__ int sidx[128];
    const uint32_t sbase = smem_u32_of(smem);

    const int tid = threadIdx.x;
    const int wid = tid >> 5, lid = tid & 31;
    const int wm  = wid >> 2;
    const int wn  = wid & 3;
    const int m0  = blockIdx.y * 128;
    const int n0  = blockIdx.x * 128;

    if (GATHER) {
        const int cnt = __ldg(cnt_p);
        if (m0 >= cnt) return;
        if (tid < 128) sidx[tid] = __ldg(&idx[min(m0 + tid, cnt - 1)]);
        __syncthreads();
    }

    const int PA[3] = {0, 0, 1};
    const int PB[3] = {0, 1, 0};
    const __nv_bfloat16* Abase[2] = {Ah, Am};
    const __nv_bfloat16* Bbase[2] = {Bh, Bm};

    const int lrow = tid >> 2;          // 0..63
    const int lch  = tid & 3;

    const int ar0 = GATHER ? sidx[lrow]      : (m0 + lrow);
    const int ar1 = GATHER ? sidx[lrow + 64] : (m0 + lrow + 64);
    const size_t aoff0 = (size_t)ar0 * DIM;
    const size_t aoff1 = (size_t)ar1 * DIM;
    const size_t boff0 = (size_t)(n0 + lrow) * DIM;
    const size_t boff1 = (size_t)(n0 + lrow + 64) * DIM;

    auto load_stage = [&](int t, int buf) {
        const int p  = t / KT;
        const int kt = t % KT;
        const size_t kofs = (size_t)kt * 32 + lch * 8;
        const __nv_bfloat16* As = Abase[PA[p]];
        const __nv_bfloat16* Bs = Bbase[PB[p]];
        const uint32_t sa = sbase + buf * STAGE;
        const uint32_t sb = sa + 8192;
        cp16(sa + swz((uint32_t)lrow * 64 + lch * 16),        As + aoff0 + kofs);
        cp16(sa + swz((uint32_t)(lrow + 64) * 64 + lch * 16), As + aoff1 + kofs);
        cp16(sb + swz((uint32_t)lrow * 64 + lch * 16),        Bs + boff0 + kofs);
        cp16(sb + swz((uint32_t)(lrow + 64) * 64 + lch * 16), Bs + boff1 + kofs);
        asm volatile("cp.async.commit_group;" ::: "memory");
    };

    float acc[4][4][4];
#pragma unroll
    for (int i = 0; i < 4; i++)
#pragma unroll
        for (int j = 0; j < 4; j++)
#pragma unroll
            for (int r = 0; r < 4; r++) acc[i][j][r] = 0.f;

    const uint32_t a_row = wm * 64 + (lid & 7) + ((lid >> 3) & 1) * 8;
    const uint32_t a_kb  = ((lid >> 4) & 1) * 16;
    const uint32_t b_row = wn * 32 + (lid & 7) + ((lid >> 4) & 1) * 8;
    const uint32_t b_kb  = ((lid >> 3) & 1) * 16;

#pragma unroll
    for (int s = 0; s < NSTG - 1; s++) load_stage(s, s);

    int buf = 0, nbuf = NSTG - 1;
    for (int t = 0; t < T; t++) {
        asm volatile("cp.async.wait_group %0;" :: "n"(NSTG - 2) : "memory");
        __syncthreads();

        const uint32_t sa = sbase + buf * STAGE;
        const uint32_t sb = sa + 8192;

#pragma unroll
        for (int ks = 0; ks < 2; ks++) {
            uint32_t af[4][4], bf[2][4];
#pragma unroll
            for (int mf = 0; mf < 4; mf++)
                ldsm_x4(af[mf], sa + swz((a_row + mf * 16) * 64 + ks * 32 + a_kb));
#pragma unroll
            for (int ng = 0; ng < 2; ng++)
                ldsm_x4(bf[ng], sb + swz((b_row + ng * 16) * 64 + ks * 32 + b_kb));
#pragma unroll
            for (int mf = 0; mf < 4; mf++)
#pragma unroll
                for (int nf = 0; nf < 4; nf++)
                    mma16816(acc[mf][nf], af[mf],
                             bf[nf >> 1][(nf & 1) * 2], bf[nf >> 1][(nf & 1) * 2 + 1]);
        }

        if (t + NSTG - 1 < T) load_stage(t + NSTG - 1, nbuf);
        if (++buf == NSTG) buf = 0;
        if (++nbuf == NSTG) nbuf = 0;
    }

    const int er = lid >> 2;
    const int ec = (lid & 3) * 2;
#pragma unroll
    for (int mf = 0; mf < 4; mf++) {
#pragma unroll
        for (int nf = 0; nf < 4; nf++) {
            const int col = n0 + wn * 32 + nf * 8 + ec;
            const float bx = __ldg(&bias[col]);
            const float by = __ldg(&bias[col + 1]);
            const int r0 = m0 + wm * 64 + mf * 16 + er;
            const int r1 = r0 + 8;
            *(float2*)(C + (size_t)r0 * DIM + col) = make_float2(acc[mf][nf][0] + bx, acc[mf][nf][1] + by);
            *(float2*)(C + (size_t)r1 * DIM + col) = make_float2(acc[mf][nf][2] + bx, acc[mf][nf][3] + by);
        }
    }
}

// ---------------------------------------------------------------------------
// fp32 -> 2-way bf16 split
// ---------------------------------------------------------------------------
__global__ __launch_bounds__(256)
void split2_kernel(const float* __restrict__ in, __nv_bfloat16* __restrict__ h,
                   __nv_bfloat16* __restrict__ m, size_t n)
{
    size_t i = ((size_t)blockIdx.x * 256 + threadIdx.x) * 4;
    if (i >= n) return;
    float4 v = *(const float4*)(in + i);
    float vv[4] = {v.x, v.y, v.z, v.w};
    __nv_bfloat16 hh[4], mm[4];
#pragma unroll
    for (int j = 0; j < 4; j++) {
        float x = vv[j];
        __nv_bfloat16 a = __float2bfloat16(x);
        float r = x - __bfloat162float(a);
        mm[j] = __float2bfloat16(r);
        hh[j] = a;
    }
    *(__nv_bfloat162*)(h + i)     = __nv_bfloat162(hh[0], hh[1]);
    *(__nv_bfloat162*)(h + i + 2) = __nv_bfloat162(hh[2], hh[3]);
    *(__nv_bfloat162*)(m + i)     = __nv_bfloat162(mm[0], mm[1]);
    *(__nv_bfloat162*)(m + i + 2) = __nv_bfloat162(mm[2], mm[3]);
}

// ---------------------------------------------------------------------------
// block reduction of two floats (256 threads)
// ---------------------------------------------------------------------------
__device__ __forceinline__ float2 block_reduce2(float a, float b)
{
    __shared__ float sa[8], sb[8];
    __syncthreads();
    int lane = threadIdx.x & 31, wd = threadIdx.x >> 5;
#pragma unroll
    for (int o = 16; o; o >>= 1) {
        a += __shfl_down_sync(0xFFFFFFFFu, a, o);
        b += __shfl_down_sync(0xFFFFFFFFu, b, o);
    }
    if (lane == 0) { sa[wd] = a; sb[wd] = b; }
    __syncthreads();
    if (wd == 0) {
        a = (lane < 8) ? sa[lane] : 0.f;
        b = (lane < 8) ? sb[lane] : 0.f;
#pragma unroll
        for (int o = 4; o; o >>= 1) {
            a += __shfl_down_sync(0xFFFFFFFFu, a, o);
            b += __shfl_down_sync(0xFFFFFFFFu, b, o);
        }
        if (lane == 0) { sa[0] = a; sb[0] = b; }
    }
    __syncthreads();
    return make_float2(sa[0], sb[0]);
}

// ---------------------------------------------------------------------------
// LN + ReLU + head, 8 rows per block, params in registers, next-row prefetch.
// ---------------------------------------------------------------------------
template<bool SCATTER>
__global__ __launch_bounds__(256)
void ln_head8(const float* __restrict__ H,
              const float* __restrict__ gamma, const float* __restrict__ beta,
              const float* __restrict__ W2, const float* __restrict__ b2,
              const int* __restrict__ idx, const int* __restrict__ cnt_p,
              float* __restrict__ out)
{
    const int base = blockIdx.x * 8;
    int cnt = BATCH;
    if (SCATTER) {
        cnt = __ldg(cnt_p);
        if (base >= cnt) return;
    }
    const int t = threadIdx.x;

    const float4* g4  = (const float4*)gamma;
    const float4* be4 = (const float4*)beta;
    const float4* w04 = (const float4*)W2;
    const float4* w14 = (const float4*)(W2 + DIM);

    const float4 ga = g4[t*2],  gb = g4[t*2+1];
    const float4 ba = be4[t*2], bb = be4[t*2+1];
    const float4 wa = w04[t*2], wb = w04[t*2+1];
    const float4 wc = w14[t*2], wd = w14[t*2+1];
    const float bias0 = __ldg(&b2[0]), bias1 = __ldg(&b2[1]);
    const float inv_d = 1.f / (float)DIM;

    // prefetch row 0
    int rr0 = SCATTER ? min(base, cnt - 1) : base;
    const float4* h4 = (const float4*)(H + (size_t)rr0 * DIM);
    float4 v0 = h4[t*2];
    float4 v1 = h4[t*2+1];

#pragma unroll 1
    for (int r = 0; r < 8; r++) {
        const int row  = base + r;
        const bool act = !SCATTER || (row < cnt);

        float s  = v0.x + v0.y + v0.z + v0.w + v1.x + v1.y + v1.z + v1.w;
        float ss = v0.x*v0.x + v0.y*v0.y + v0.z*v0.z + v0.w*v0.w
                 + v1.x*v1.x + v1.y*v1.y + v1.z*v1.z + v1.w*v1.w;

        // issue next row's loads before the barriers
        float4 n0v, n1v;
        if (r < 7) {
            const int nrow = base + r + 1;
            const int nrr  = SCATTER ? min(nrow, cnt - 1) : nrow;
            const float4* nh4 = (const float4*)(H + (size_t)nrr * DIM);
            n0v = nh4[t*2];
            n1v = nh4[t*2+1];
        }

        float2 red = block_reduce2(s, ss);
        float mu   = red.x * inv_d;
        float var  = red.y * inv_d - mu * mu;
        float rinv = rsqrtf(var + 1e-5f);

        float l0 = 0.f, l1 = 0.f, h;
        h = fmaxf(fmaf((v0.x - mu)*rinv, ga.x, ba.x), 0.f); l0 += h*wa.x; l1 += h*wc.x;
        h = fmaxf(fmaf((v0.y - mu)*rinv, ga.y, ba.y), 0.f); l0 += h*wa.y; l1 += h*wc.y;
        h = fmaxf(fmaf((v0.z - mu)*rinv, ga.z, ba.z), 0.f); l0 += h*wa.z; l1 += h*wc.z;
        h = fmaxf(fmaf((v0.w - mu)*rinv, ga.w, ba.w), 0.f); l0 += h*wa.w; l1 += h*wc.w;
        h = fmaxf(fmaf((v1.x - mu)*rinv, gb.x, bb.x), 0.f); l0 += h*wb.x; l1 += h*wd.x;
        h = fmaxf(fmaf((v1.y - mu)*rinv, gb.y, bb.y), 0.f); l0 += h*wb.y; l1 += h*wd.y;
        h = fmaxf(fmaf((v1.z - mu)*rinv, gb.z, bb.z), 0.f); l0 += h*wb.z; l1 += h*wd.z;
        h = fmaxf(fmaf((v1.w - mu)*rinv, gb.w, bb.w), 0.f); l0 += h*wb.w; l1 += h*wd.w;

        float2 lr = block_reduce2(l0, l1);
        if (t == 0 && act) {
            if (SCATTER) {
                const int o = __ldg(&idx[row]);
                out[o*2]   = lr.x + bias0;
                out[o*2+1] = lr.y + bias1;
            } else {
                out[row*2]   = lr.x + bias0;
                out[row*2+1] = lr.y + bias1;
            }
        }
        v0 = n0v;
        v1 = n1v;
    }
}

// ---------------------------------------------------------------------------
// Flag rows with |l0-l1| < thresh. Single block, ordered compaction.
// ---------------------------------------------------------------------------
__global__ __launch_bounds__(1024)
void flag_scan(const float* __restrict__ L0, float thresh, int cap,
               int* __restrict__ rlist, int* __restrict__ rcnt)
{
    __shared__ int sf[1024];
    const int t = threadIdx.x;
    uint32_t mask = 0;
    int c = 0;
#pragma unroll
    for (int j = 0; j < 32; j++) {
        const int b = t * 32 + j;
        float2 f = ((const float2*)L0)[b];
        const bool fl = fabsf(f.x - f.y) < thresh;
        mask |= (uint32_t)fl << j;
        c += fl;
    }
    sf[t] = c;
    __syncthreads();
    for (int off = 1; off < 1024; off <<= 1) {
        int v = (t >= off) ? sf[t - off] : 0;
        __syncthreads();
        sf[t] += v;
        __syncthreads();
    }
    int pos = sf[t] - c;
#pragma unroll
    for (int j = 0; j < 32; j++) {
        if ((mask >> j) & 1) {
            if (pos < cap) rlist[pos] = t * 32 + j;
            pos++;
        }
    }
    if (t == 1023) rcnt[0] = min(sf[1023], cap);
}

// ---------------------------------------------------------------------------
// Exact fp32 recompute of h = x@W1.T + b1 for flagged rows (column-parallel).
// ---------------------------------------------------------------------------
__global__ __launch_bounds__(256)
void refine_h(const float* __restrict__ x, const float* __restrict__ W1,
              const float* __restrict__ b1,
              const int* __restrict__ rlist, const int* __restrict__ rcnt,
              float* __restrict__ Hr)
{
    const int slot = blockIdx.y;
    if (slot >= __ldg(rcnt)) return;
    const int row = __ldg(&rlist[slot]);

    __shared__ float sx[DIM];
    const int tid = threadIdx.x, wid = tid >> 5, lane = tid & 31;
    for (int i = tid; i < DIM; i += 256) sx[i] = x[(size_t)row * DIM + i];
    __syncthreads();

    const int col0 = blockIdx.x * 64;
#pragma unroll 1
    for (int c = wid; c < 64; c += 8) {
        const int j = col0 + c;
        const float* wr = W1 + (size_t)j * DIM;
        float acc = 0.f;
#pragma unroll 8
        for (int k = lane; k < DIM; k += 32)
            acc = fmaf(sx[k], __ldg(&wr[k]), acc);
#pragma unroll
        for (int o = 16; o; o >>= 1) acc += __shfl_down_sync(0xFFFFFFFFu, acc, o);
        if (lane == 0) Hr[(size_t)slot * DIM + j] = acc + __ldg(&b1[j]);
    }
}

// LN + head from exact h; patch L[row]. One block per slot.
__global__ __launch_bounds__(256)
void refine_fix(const float* __restrict__ Hr,
                const float* __restrict__ gamma, const float* __restrict__ beta,
                const float* __restrict__ W2, const float* __restrict__ b2,
                const int* __restrict__ rlist, const int* __restrict__ rcnt,
                float* __restrict__ L)
{
    const int slot = blockIdx.x;
    if (slot >= __ldg(rcnt)) return;
    const int t = threadIdx.x;
    const float4* h4 = (const float4*)(Hr + (size_t)slot * DIM);
    float4 v0 = h4[t*2];
    float4 v1 = h4[t*2+1];

    float s  = v0.x + v0.y + v0.z + v0.w + v1.x + v1.y + v1.z + v1.w;
    float ss = v0.x*v0.x + v0.y*v0.y + v0.z*v0.z + v0.w*v0.w
             + v1.x*v1.x + v1.y*v1.y + v1.z*v1.z + v1.w*v1.w;
    float2 red = block_reduce2(s, ss);
    const float inv_d = 1.f / (float)DIM;
    float mu = red.x * inv_d, var = red.y * inv_d - mu * mu;
    float rinv = rsqrtf(var + 1e-5f);

    const float4* g4  = (const float4*)gamma;
    const float4* be4 = (const float4*)beta;
    const float4* w04 = (const float4*)W2;
    const float4* w14 = (const float4*)(W2 + DIM);

    float l0 = 0.f, l1 = 0.f;
#pragma unroll
    for (int q = 0; q < 2; q++) {
        float4 v  = q ? v1 : v0;
        float4 g  = g4[t*2+q], be = be4[t*2+q], wa = w04[t*2+q], wbv = w14[t*2+q];
        float h;
        h = fmaxf(fmaf((v.x - mu)*rinv, g.x, be.x), 0.f); l0 += h*wa.x; l1 += h*wbv.x;
        h = fmaxf(fmaf((v.y - mu)*rinv, g.y, be.y), 0.f); l0 += h*wa.y; l1 += h*wbv.y;
        h = fmaxf(fmaf((v.z - mu)*rinv, g.z, be.z), 0.f); l0 += h*wa.z; l1 += h*wbv.z;
        h = fmaxf(fmaf((v.w - mu)*rinv, g.w, be.w), 0.f); l0 += h*wa.w; l1 += h*wbv.w;
    }
    float2 lr = block_reduce2(l0, l1);
    if (t == 0) {
        const int row = __ldg(&rlist[slot]);
        L[row*2]   = lr.x + __ldg(&b2[0]);
        L[row*2+1] = lr.y + __ldg(&b2[1]);
    }
}

// ---------------------------------------------------------------------------
// Deterministic route compaction: 1 block, 1024 threads, 32 rows each.
// ---------------------------------------------------------------------------
__global__ __launch_bounds__(1024)
void route_scan(const float* __restrict__ L0, int* __restrict__ fake_idx,
                int* __restrict__ real_idx, int* __restrict__ cnts)
{
    __shared__ int sf[1024];
    const int t = threadIdx.x;
    uint32_t mask = 0;
    int c = 0;
#pragma unroll
    for (int j = 0; j < 32; j++) {
        const int b = t * 32 + j;
        float2 f = ((const float2*)L0)[b];
        const bool fake = (f.x >= f.y);
        mask |= (uint32_t)fake << j;
        c += fake;
    }
    sf[t] = c;
    __syncthreads();
    for (int off = 1; off < 1024; off <<= 1) {
        int v = (t >= off) ? sf[t - off] : 0;
        __syncthreads();
        sf[t] += v;
        __syncthreads();
    }
    const int total_fake = sf[1023];
    const int excl = sf[t] - c;
    int fpos = excl;
#pragma unroll
    for (int j = 0; j < 32; j++) {
        const int b = t * 32 + j;
        if ((mask >> j) & 1) {
            fake_idx[fpos++] = b;
        } else {
            const int fake_before = excl + __popc(mask & ((1u << j) - 1u));
            real_idx[b - fake_before] = b;
        }
    }
    if (t == 0) { cnts[0] = total_fake; cnts[1] = BATCH - total_fake; }
}

// ---------------------------------------------------------------------------
extern "C" void kernel_launch(void* const* d_in, const int* in_sizes, int n_in,
                              void* d_out, int out_size)
{
    (void)in_sizes; (void)n_in; (void)out_size;
    const float* x = (const float*)d_in[0];

    float *H = nullptr, *L = nullptr, *Hr = nullptr;
    __nv_bfloat16 *xs = nullptr, *ws = nullptr;
    int *idx = nullptr, *cnt = nullptr;
    int *rl1 = nullptr, *rc1 = nullptr, *rl2 = nullptr, *rc2 = nullptr;
    cudaGetSymbolAddress((void**)&H,   g_H);
    cudaGetSymbolAddress((void**)&L,   g_logits);
    cudaGetSymbolAddress((void**)&Hr,  g_Hr);
    cudaGetSymbolAddress((void**)&xs,  g_xs);
    cudaGetSymbolAddress((void**)&ws,  g_ws);
    cudaGetSymbolAddress((void**)&idx, g_idx);
    cudaGetSymbolAddress((void**)&cnt, g_cnt);
    cudaGetSymbolAddress((void**)&rl1, g_rlist1);
    cudaGetSymbolAddress((void**)&rc1, g_rcnt1);
    cudaGetSymbolAddress((void**)&rl2, g_rlist2);
    cudaGetSymbolAddress((void**)&rc2, g_rcnt2);

    const size_t XN = (size_t)BATCH * DIM;
    const size_t WN = (size_t)DIM * DIM;
    __nv_bfloat16 *xh = xs, *xm = xs + XN;
    __nv_bfloat16 *wh = ws, *wm = ws + WN;

    constexpr int SMEM_BYTES = NSTG * 16384;   // 96 KB
    cudaFuncSetAttribute(gemm_mma<1,false>, cudaFuncAttributeMaxDynamicSharedMemorySize, SMEM_BYTES);
    cudaFuncSetAttribute(gemm_mma<3,true>,  cudaFuncAttributeMaxDynamicSharedMemorySize, SMEM_BYTES);

    split2_kernel<<<(int)(XN / 4 / 256), 256>>>(x, xh, xm, XN);

    dim3 grid(DIM / 128, BATCH / 128);        // (16, 256)
    dim3 grid_t1(DIM / 128, RCAP1 / 128);     // (16, 64)

    // ---- first (routing) branch: 1-product GEMM + tiered refine ----
    {
        const float* W1 = (const float*)d_in[1];
        const float* b1 = (const float*)d_in[2];
        const float* lg = (const float*)d_in[3];
        const float* lb = (const float*)d_in[4];
        const float* W2 = (const float*)d_in[5];
        const float* b2 = (const float*)d_in[6];
        split2_kernel<<<(int)(WN / 4 / 256), 256>>>(W1, wh, wm, WN);

        // tier-0: 1-product (hi*hi) full-batch GEMM (gap error sigma ~2.3e-3)
        gemm_mma<1,false><<<grid, 256, SMEM_BYTES>>>(xh, xm, wh, wm, b1, H,
                                                     nullptr, nullptr);
        ln_head8<false><<<BATCH / 8, 256>>>(H, lg, lb, W2, b2, nullptr, nullptr, L);

        // tier-1: |gap| < 2e-2 (~8.7 sigma) -> 3-product recompute, patch L
        flag_scan<<<1, 1024>>>(L, 2e-2f, RCAP1, rl1, rc1);
        gemm_mma<3,true><<<grid_t1, 256, SMEM_BYTES>>>(xh, xm, wh, wm, b1, H,
                                                       rl1, rc1);
        ln_head8<true><<<RCAP1 / 8, 256>>>(H, lg, lb, W2, b2, rl1, rc1, L);

        // tier-2: |gap| < 1e-3 -> exact fp32 recompute, patch L
        flag_scan<<<1, 1024>>>(L, 1e-3f, RCAP2, rl2, rc2);
        refine_h<<<dim3(32, RCAP2), 256>>>(x, W1, b1, rl2, rc2, Hr);
        refine_fix<<<RCAP2, 256>>>(Hr, lg, lb, W2, b2, rl2, rc2, L);
    }

    route_scan<<<1, 1024>>>(L, idx, idx + BATCH, cnt);

    // ---- fake (route==0) and real branches: only their rows, 3 products ----
    for (int br = 1; br < 3; br++) {
        const float* W1 = (const float*)d_in[1 + br * 6 + 0];
        const float* b1 = (const float*)d_in[1 + br * 6 + 1];
        const float* lg = (const float*)d_in[1 + br * 6 + 2];
        const float* lb = (const float*)d_in[1 + br * 6 + 3];
        const float* W2 = (const float*)d_in[1 + br * 6 + 4];
        const float* b2 = (const float*)d_in[1 + br * 6 + 5];

        split2_kernel<<<(int)(WN / 4 / 256), 256>>>(W1, wh, wm, WN);

        int* bidx = idx + (br - 1) * BATCH;
        int* bcnt = cnt + (br - 1);
        gemm_mma<3,true><<<grid, 256, SMEM_BYTES>>>(xh, xm, wh, wm, b1, H,
                                                    bidx, bcnt);
        ln_head8<true><<<BATCH / 8, 256>>>(H, lg, lb, W2, b2, bidx, bcnt,
                                           (float*)d_out);
    }
}

// round 13
// speedup vs baseline: 1.5542x; 1.0411x over previous
#include <cuda_runtime.h>
#include <cuda_bf16.h>
#include <cstdint>

#define DIM   2048
#define BATCH 32768
#define RCAP1 8192
#define RCAP2 256
#define NSTG  6              // pipeline depth for 1-product kernel
#define NSF   3              // pipeline depth for fused 3-product kernel (32KB/stage)

// ---------------------------------------------------------------------------
// Device-global scratch
// ---------------------------------------------------------------------------
__device__ __align__(16) float g_H[(size_t)BATCH * DIM];
__device__ __align__(16) float g_logits[BATCH * 2];
__device__ __align__(16) __nv_bfloat16 g_xs[2][(size_t)BATCH * DIM];
__device__ __align__(16) __nv_bfloat16 g_ws[2][(size_t)DIM * DIM];
__device__ __align__(16) float g_Hr[(size_t)RCAP2 * DIM];
__device__ int g_idx[2][BATCH];
__device__ int g_cnt[2];
__device__ int g_rlist1[RCAP1];
__device__ int g_rcnt1[1];
__device__ int g_rlist2[RCAP2];
__device__ int g_rcnt2[1];

// ---------------------------------------------------------------------------
// helpers
// ---------------------------------------------------------------------------
__device__ __forceinline__ uint32_t smem_u32_of(const void* p) {
    uint32_t a;
    asm("{ .reg .u64 t; cvta.to.shared.u64 t, %1; cvt.u32.u64 %0, t; }" : "=r"(a) : "l"(p));
    return a;
}
__device__ __forceinline__ void cp16(uint32_t dst, const void* src) {
    asm volatile("cp.async.cg.shared.global [%0], [%1], 16;" :: "r"(dst), "l"(src));
}
__device__ __forceinline__ void ldsm_x4(uint32_t* r, uint32_t addr) {
    asm volatile("ldmatrix.sync.aligned.m8n8.x4.shared.b16 {%0,%1,%2,%3}, [%4];"
                 : "=r"(r[0]), "=r"(r[1]), "=r"(r[2]), "=r"(r[3]) : "r"(addr));
}
__device__ __forceinline__ void mma16816(float* c, const uint32_t* a,
                                         uint32_t b0, uint32_t b1) {
    asm volatile("mma.sync.aligned.m16n8k16.row.col.f32.bf16.bf16.f32 "
                 "{%0,%1,%2,%3}, {%4,%5,%6,%7}, {%8,%9}, {%0,%1,%2,%3};"
                 : "+f"(c[0]), "+f"(c[1]), "+f"(c[2]), "+f"(c[3])
                 : "r"(a[0]), "r"(a[1]), "r"(a[2]), "r"(a[3]), "r"(b0), "r"(b1));
}
__device__ __forceinline__ uint32_t swz(uint32_t off) {       // Swizzle<3,4,3>
    return off ^ (((off >> 7) & 7u) << 4);
}

// ---------------------------------------------------------------------------
// 1-product bf16 GEMM (tier-0 routing): C = A_hi @ B_hi^T + bias
// R9-proven config: tile 128x128, 8 warps, NSTG-stage cp.async, 2 CTAs/SM.
// ---------------------------------------------------------------------------
__global__ __launch_bounds__(256)
void gemm_mma1(const __nv_bfloat16* __restrict__ Ah,
               const __nv_bfloat16* __restrict__ Bh,
               const float* __restrict__ bias, float* __restrict__ C)
{
    constexpr int KT    = DIM / 32;
    constexpr int STAGE = 16384;

    extern __shared__ __align__(128) char smem[];
    const uint32_t sbase = smem_u32_of(smem);

    const int tid = threadIdx.x;
    const int wid = tid >> 5, lid = tid & 31;
    const int wm  = wid >> 2;
    const int wn  = wid & 3;
    const int m0  = blockIdx.y * 128;
    const int n0  = blockIdx.x * 128;

    const int lrow = tid >> 2;
    const int lch  = tid & 3;

    const size_t aoff0 = (size_t)(m0 + lrow) * DIM;
    const size_t aoff1 = (size_t)(m0 + lrow + 64) * DIM;
    const size_t boff0 = (size_t)(n0 + lrow) * DIM;
    const size_t boff1 = (size_t)(n0 + lrow + 64) * DIM;

    auto load_stage = [&](int kt, int buf) {
        const size_t kofs = (size_t)kt * 32 + lch * 8;
        const uint32_t sa = sbase + buf * STAGE;
        const uint32_t sb = sa + 8192;
        cp16(sa + swz((uint32_t)lrow * 64 + lch * 16),        Ah + aoff0 + kofs);
        cp16(sa + swz((uint32_t)(lrow + 64) * 64 + lch * 16), Ah + aoff1 + kofs);
        cp16(sb + swz((uint32_t)lrow * 64 + lch * 16),        Bh + boff0 + kofs);
        cp16(sb + swz((uint32_t)(lrow + 64) * 64 + lch * 16), Bh + boff1 + kofs);
        asm volatile("cp.async.commit_group;" ::: "memory");
    };

    float acc[4][4][4];
#pragma unroll
    for (int i = 0; i < 4; i++)
#pragma unroll
        for (int j = 0; j < 4; j++)
#pragma unroll
            for (int r = 0; r < 4; r++) acc[i][j][r] = 0.f;

    const uint32_t a_row = wm * 64 + (lid & 7) + ((lid >> 3) & 1) * 8;
    const uint32_t a_kb  = ((lid >> 4) & 1) * 16;
    const uint32_t b_row = wn * 32 + (lid & 7) + ((lid >> 4) & 1) * 8;
    const uint32_t b_kb  = ((lid >> 3) & 1) * 16;

#pragma unroll
    for (int s = 0; s < NSTG - 1; s++) load_stage(s, s);

    int buf = 0, nbuf = NSTG - 1;
    for (int t = 0; t < KT; t++) {
        asm volatile("cp.async.wait_group %0;" :: "n"(NSTG - 2) : "memory");
        __syncthreads();

        const uint32_t sa = sbase + buf * STAGE;
        const uint32_t sb = sa + 8192;

#pragma unroll
        for (int ks = 0; ks < 2; ks++) {
            uint32_t af[4][4], bf[2][4];
#pragma unroll
            for (int mf = 0; mf < 4; mf++)
                ldsm_x4(af[mf], sa + swz((a_row + mf * 16) * 64 + ks * 32 + a_kb));
#pragma unroll
            for (int ng = 0; ng < 2; ng++)
                ldsm_x4(bf[ng], sb + swz((b_row + ng * 16) * 64 + ks * 32 + b_kb));
#pragma unroll
            for (int mf = 0; mf < 4; mf++)
#pragma unroll
                for (int nf = 0; nf < 4; nf++)
                    mma16816(acc[mf][nf], af[mf],
                             bf[nf >> 1][(nf & 1) * 2], bf[nf >> 1][(nf & 1) * 2 + 1]);
        }

        if (t + NSTG - 1 < KT) load_stage(t + NSTG - 1, nbuf);
        if (++buf == NSTG) buf = 0;
        if (++nbuf == NSTG) nbuf = 0;
    }

    const int er = lid >> 2;
    const int ec = (lid & 3) * 2;
#pragma unroll
    for (int mf = 0; mf < 4; mf++) {
#pragma unroll
        for (int nf = 0; nf < 4; nf++) {
            const int col = n0 + wn * 32 + nf * 8 + ec;
            const float bx = __ldg(&bias[col]);
            const float by = __ldg(&bias[col + 1]);
            const int r0 = m0 + wm * 64 + mf * 16 + er;
            const int r1 = r0 + 8;
            *(float2*)(C + (size_t)r0 * DIM + col) = make_float2(acc[mf][nf][0] + bx, acc[mf][nf][1] + by);
            *(float2*)(C + (size_t)r1 * DIM + col) = make_float2(acc[mf][nf][2] + bx, acc[mf][nf][3] + by);
        }
    }
}

// ---------------------------------------------------------------------------
// FUSED 3-product bf16 GEMM: per k-tile, load A_hi/A_mid/B_hi/B_mid once
// (32KB stage) and accumulate hh + hm + mh. Tile 128x128, 8 warps, NSF-stage
// cp.async, 2 CTAs/SM pinned. 33% less smem/global traffic vs product-major.
// ---------------------------------------------------------------------------
template<bool GATHER>
__global__ __launch_bounds__(256, 2)
void gemm_mma3f(const __nv_bfloat16* __restrict__ Ah, const __nv_bfloat16* __restrict__ Am,
                const __nv_bfloat16* __restrict__ Bh, const __nv_bfloat16* __restrict__ Bm,
                const float* __restrict__ bias, float* __restrict__ C,
                const int* __restrict__ idx, const int* __restrict__ cnt_p)
{
    constexpr int KT    = DIM / 32;
    constexpr int STAGE = 32768;    // 4 x 8KB tiles: A_hi, A_mid, B_hi, B_mid

    extern __shared__ __align__(128) char smem[];
    __shared__ int sidx[128];
    const uint32_t sbase = smem_u32_of(smem);

    const int tid = threadIdx.x;
    const int wid = tid >> 5, lid = tid & 31;
    const int wm  = wid >> 2;
    const int wn  = wid & 3;
    const int m0  = blockIdx.y * 128;
    const int n0  = blockIdx.x * 128;

    if (GATHER) {
        const int cnt = __ldg(cnt_p);
        if (m0 >= cnt) return;
        if (tid < 128) sidx[tid] = __ldg(&idx[min(m0 + tid, cnt - 1)]);
        __syncthreads();
    }

    const int lrow = tid >> 2;
    const int lch  = tid & 3;

    const int ar0 = GATHER ? sidx[lrow]      : (m0 + lrow);
    const int ar1 = GATHER ? sidx[lrow + 64] : (m0 + lrow + 64);
    const size_t aoff0 = (size_t)ar0 * DIM;
    const size_t aoff1 = (size_t)ar1 * DIM;
    const size_t boff0 = (size_t)(n0 + lrow) * DIM;
    const size_t boff1 = (size_t)(n0 + lrow + 64) * DIM;

    auto load_stage = [&](int kt, int buf) {
        const size_t kofs = (size_t)kt * 32 + lch * 8;
        const uint32_t s0 = sbase + buf * STAGE;            // A_hi
        const uint32_t s1 = s0 + 8192;                      // A_mid
        const uint32_t s2 = s0 + 16384;                     // B_hi
        const uint32_t s3 = s0 + 24576;                     // B_mid
        const uint32_t o0 = swz((uint32_t)lrow * 64 + lch * 16);
        const uint32_t o1 = swz((uint32_t)(lrow + 64) * 64 + lch * 16);
        cp16(s0 + o0, Ah + aoff0 + kofs);
        cp16(s0 + o1, Ah + aoff1 + kofs);
        cp16(s1 + o0, Am + aoff0 + kofs);
        cp16(s1 + o1, Am + aoff1 + kofs);
        cp16(s2 + o0, Bh + boff0 + kofs);
        cp16(s2 + o1, Bh + boff1 + kofs);
        cp16(s3 + o0, Bm + boff0 + kofs);
        cp16(s3 + o1, Bm + boff1 + kofs);
        asm volatile("cp.async.commit_group;" ::: "memory");
    };

    float acc[4][4][4];
#pragma unroll
    for (int i = 0; i < 4; i++)
#pragma unroll
        for (int j = 0; j < 4; j++)
#pragma unroll
            for (int r = 0; r < 4; r++) acc[i][j][r] = 0.f;

    const uint32_t a_row = wm * 64 + (lid & 7) + ((lid >> 3) & 1) * 8;
    const uint32_t a_kb  = ((lid >> 4) & 1) * 16;
    const uint32_t b_row = wn * 32 + (lid & 7) + ((lid >> 4) & 1) * 8;
    const uint32_t b_kb  = ((lid >> 3) & 1) * 16;

#pragma unroll
    for (int s = 0; s < NSF - 1; s++) load_stage(s, s);

    int buf = 0, nbuf = NSF - 1;
    for (int t = 0; t < KT; t++) {
        asm volatile("cp.async.wait_group %0;" :: "n"(NSF - 2) : "memory");
        __syncthreads();

        const uint32_t sAh = sbase + buf * STAGE;
        const uint32_t sAm = sAh + 8192;
        const uint32_t sBh = sAh + 16384;
        const uint32_t sBm = sAh + 24576;

#pragma unroll
        for (int ks = 0; ks < 2; ks++) {
            uint32_t bh[2][4], bm[2][4];
#pragma unroll
            for (int ng = 0; ng < 2; ng++) {
                ldsm_x4(bh[ng], sBh + swz((b_row + ng * 16) * 64 + ks * 32 + b_kb));
                ldsm_x4(bm[ng], sBm + swz((b_row + ng * 16) * 64 + ks * 32 + b_kb));
            }
            // hh + hm: A_hi fragments, one mf at a time (register reuse)
#pragma unroll
            for (int mf = 0; mf < 4; mf++) {
                uint32_t a[4];
                ldsm_x4(a, sAh + swz((a_row + mf * 16) * 64 + ks * 32 + a_kb));
#pragma unroll
                for (int nf = 0; nf < 4; nf++)
                    mma16816(acc[mf][nf], a,
                             bh[nf >> 1][(nf & 1) * 2], bh[nf >> 1][(nf & 1) * 2 + 1]);
#pragma unroll
                for (int nf = 0; nf < 4; nf++)
                    mma16816(acc[mf][nf], a,
                             bm[nf >> 1][(nf & 1) * 2], bm[nf >> 1][(nf & 1) * 2 + 1]);
            }
            // mh: A_mid fragments x B_hi
#pragma unroll
            for (int mf = 0; mf < 4; mf++) {
                uint32_t a[4];
                ldsm_x4(a, sAm + swz((a_row + mf * 16) * 64 + ks * 32 + a_kb));
#pragma unroll
                for (int nf = 0; nf < 4; nf++)
                    mma16816(acc[mf][nf], a,
                             bh[nf >> 1][(nf & 1) * 2], bh[nf >> 1][(nf & 1) * 2 + 1]);
            }
        }

        if (t + NSF - 1 < KT) load_stage(t + NSF - 1, nbuf);
        if (++buf == NSF) buf = 0;
        if (++nbuf == NSF) nbuf = 0;
    }

    const int er = lid >> 2;
    const int ec = (lid & 3) * 2;
#pragma unroll
    for (int mf = 0; mf < 4; mf++) {
#pragma unroll
        for (int nf = 0; nf < 4; nf++) {
            const int col = n0 + wn * 32 + nf * 8 + ec;
            const float bx = __ldg(&bias[col]);
            const float by = __ldg(&bias[col + 1]);
            const int r0 = m0 + wm * 64 + mf * 16 + er;
            const int r1 = r0 + 8;
            *(float2*)(C + (size_t)r0 * DIM + col) = make_float2(acc[mf][nf][0] + bx, acc[mf][nf][1] + by);
            *(float2*)(C + (size_t)r1 * DIM + col) = make_float2(acc[mf][nf][2] + bx, acc[mf][nf][3] + by);
        }
    }
}

// ---------------------------------------------------------------------------
// fp32 -> 2-way bf16 split
// ---------------------------------------------------------------------------
__global__ __launch_bounds__(256)
void split2_kernel(const float* __restrict__ in, __nv_bfloat16* __restrict__ h,
                   __nv_bfloat16* __restrict__ m, size_t n)
{
    size_t i = ((size_t)blockIdx.x * 256 + threadIdx.x) * 4;
    if (i >= n) return;
    float4 v = *(const float4*)(in + i);
    float vv[4] = {v.x, v.y, v.z, v.w};
    __nv_bfloat16 hh[4], mm[4];
#pragma unroll
    for (int j = 0; j < 4; j++) {
        float x = vv[j];
        __nv_bfloat16 a = __float2bfloat16(x);
        float r = x - __bfloat162float(a);
        mm[j] = __float2bfloat16(r);
        hh[j] = a;
    }
    *(__nv_bfloat162*)(h + i)     = __nv_bfloat162(hh[0], hh[1]);
    *(__nv_bfloat162*)(h + i + 2) = __nv_bfloat162(hh[2], hh[3]);
    *(__nv_bfloat162*)(m + i)     = __nv_bfloat162(mm[0], mm[1]);
    *(__nv_bfloat162*)(m + i + 2) = __nv_bfloat162(mm[2], mm[3]);
}

// ---------------------------------------------------------------------------
// block reduction of two floats (256 threads)
// ---------------------------------------------------------------------------
__device__ __forceinline__ float2 block_reduce2(float a, float b)
{
    __shared__ float sa[8], sb[8];
    __syncthreads();
    int lane = threadIdx.x & 31, wd = threadIdx.x >> 5;
#pragma unroll
    for (int o = 16; o; o >>= 1) {
        a += __shfl_down_sync(0xFFFFFFFFu, a, o);
        b += __shfl_down_sync(0xFFFFFFFFu, b, o);
    }
    if (lane == 0) { sa[wd] = a; sb[wd] = b; }
    __syncthreads();
    if (wd == 0) {
        a = (lane < 8) ? sa[lane] : 0.f;
        b = (lane < 8) ? sb[lane] : 0.f;
#pragma unroll
        for (int o = 4; o; o >>= 1) {
            a += __shfl_down_sync(0xFFFFFFFFu, a, o);
            b += __shfl_down_sync(0xFFFFFFFFu, b, o);
        }
        if (lane == 0) { sa[0] = a; sb[0] = b; }
    }
    __syncthreads();
    return make_float2(sa[0], sb[0]);
}

// ---------------------------------------------------------------------------
// LN + ReLU + head, 8 rows per block, params in registers, next-row prefetch.
// ---------------------------------------------------------------------------
template<bool SCATTER>
__global__ __launch_bounds__(256)
void ln_head8(const float* __restrict__ H,
              const float* __restrict__ gamma, const float* __restrict__ beta,
              const float* __restrict__ W2, const float* __restrict__ b2,
              const int* __restrict__ idx, const int* __restrict__ cnt_p,
              float* __restrict__ out)
{
    const int base = blockIdx.x * 8;
    int cnt = BATCH;
    if (SCATTER) {
        cnt = __ldg(cnt_p);
        if (base >= cnt) return;
    }
    const int t = threadIdx.x;

    const float4* g4  = (const float4*)gamma;
    const float4* be4 = (const float4*)beta;
    const float4* w04 = (const float4*)W2;
    const float4* w14 = (const float4*)(W2 + DIM);

    const float4 ga = g4[t*2],  gb = g4[t*2+1];
    const float4 ba = be4[t*2], bb = be4[t*2+1];
    const float4 wa = w04[t*2], wb = w04[t*2+1];
    const float4 wc = w14[t*2], wd = w14[t*2+1];
    const float bias0 = __ldg(&b2[0]), bias1 = __ldg(&b2[1]);
    const float inv_d = 1.f / (float)DIM;

    int rr0 = SCATTER ? min(base, cnt - 1) : base;
    const float4* h4 = (const float4*)(H + (size_t)rr0 * DIM);
    float4 v0 = h4[t*2];
    float4 v1 = h4[t*2+1];

#pragma unroll 1
    for (int r = 0; r < 8; r++) {
        const int row  = base + r;
        const bool act = !SCATTER || (row < cnt);

        float s  = v0.x + v0.y + v0.z + v0.w + v1.x + v1.y + v1.z + v1.w;
        float ss = v0.x*v0.x + v0.y*v0.y + v0.z*v0.z + v0.w*v0.w
                 + v1.x*v1.x + v1.y*v1.y + v1.z*v1.z + v1.w*v1.w;

        float4 n0v, n1v;
        if (r < 7) {
            const int nrow = base + r + 1;
            const int nrr  = SCATTER ? min(nrow, cnt - 1) : nrow;
            const float4* nh4 = (const float4*)(H + (size_t)nrr * DIM);
            n0v = nh4[t*2];
            n1v = nh4[t*2+1];
        }

        float2 red = block_reduce2(s, ss);
        float mu   = red.x * inv_d;
        float var  = red.y * inv_d - mu * mu;
        float rinv = rsqrtf(var + 1e-5f);

        float l0 = 0.f, l1 = 0.f, h;
        h = fmaxf(fmaf((v0.x - mu)*rinv, ga.x, ba.x), 0.f); l0 += h*wa.x; l1 += h*wc.x;
        h = fmaxf(fmaf((v0.y - mu)*rinv, ga.y, ba.y), 0.f); l0 += h*wa.y; l1 += h*wc.y;
        h = fmaxf(fmaf((v0.z - mu)*rinv, ga.z, ba.z), 0.f); l0 += h*wa.z; l1 += h*wc.z;
        h = fmaxf(fmaf((v0.w - mu)*rinv, ga.w, ba.w), 0.f); l0 += h*wa.w; l1 += h*wc.w;
        h = fmaxf(fmaf((v1.x - mu)*rinv, gb.x, bb.x), 0.f); l0 += h*wb.x; l1 += h*wd.x;
        h = fmaxf(fmaf((v1.y - mu)*rinv, gb.y, bb.y), 0.f); l0 += h*wb.y; l1 += h*wd.y;
        h = fmaxf(fmaf((v1.z - mu)*rinv, gb.z, bb.z), 0.f); l0 += h*wb.z; l1 += h*wd.z;
        h = fmaxf(fmaf((v1.w - mu)*rinv, gb.w, bb.w), 0.f); l0 += h*wb.w; l1 += h*wd.w;

        float2 lr = block_reduce2(l0, l1);
        if (t == 0 && act) {
            if (SCATTER) {
                const int o = __ldg(&idx[row]);
                out[o*2]   = lr.x + bias0;
                out[o*2+1] = lr.y + bias1;
            } else {
                out[row*2]   = lr.x + bias0;
                out[row*2+1] = lr.y + bias1;
            }
        }
        v0 = n0v;
        v1 = n1v;
    }
}

// ---------------------------------------------------------------------------
// Flag rows with |l0-l1| < thresh. Single block, ordered compaction.
// ---------------------------------------------------------------------------
__global__ __launch_bounds__(1024)
void flag_scan(const float* __restrict__ L0, float thresh, int cap,
               int* __restrict__ rlist, int* __restrict__ rcnt)
{
    __shared__ int sf[1024];
    const int t = threadIdx.x;
    uint32_t mask = 0;
    int c = 0;
#pragma unroll
    for (int j = 0; j < 32; j++) {
        const int b = t * 32 + j;
        float2 f = ((const float2*)L0)[b];
        const bool fl = fabsf(f.x - f.y) < thresh;
        mask |= (uint32_t)fl << j;
        c += fl;
    }
    sf[t] = c;
    __syncthreads();
    for (int off = 1; off < 1024; off <<= 1) {
        int v = (t >= off) ? sf[t - off] : 0;
        __syncthreads();
        sf[t] += v;
        __syncthreads();
    }
    int pos = sf[t] - c;
#pragma unroll
    for (int j = 0; j < 32; j++) {
        if ((mask >> j) & 1) {
            if (pos < cap) rlist[pos] = t * 32 + j;
            pos++;
        }
    }
    if (t == 1023) rcnt[0] = min(sf[1023], cap);
}

// ---------------------------------------------------------------------------
// Exact fp32 recompute of h = x@W1.T + b1 for flagged rows (column-parallel).
// ---------------------------------------------------------------------------
__global__ __launch_bounds__(256)
void refine_h(const float* __restrict__ x, const float* __restrict__ W1,
              const float* __restrict__ b1,
              const int* __restrict__ rlist, const int* __restrict__ rcnt,
              float* __restrict__ Hr)
{
    const int slot = blockIdx.y;
    if (slot >= __ldg(rcnt)) return;
    const int row = __ldg(&rlist[slot]);

    __shared__ float sx[DIM];
    const int tid = threadIdx.x, wid = tid >> 5, lane = tid & 31;
    for (int i = tid; i < DIM; i += 256) sx[i] = x[(size_t)row * DIM + i];
    __syncthreads();

    const int col0 = blockIdx.x * 64;
#pragma unroll 1
    for (int c = wid; c < 64; c += 8) {
        const int j = col0 + c;
        const float* wr = W1 + (size_t)j * DIM;
        float acc = 0.f;
#pragma unroll 8
        for (int k = lane; k < DIM; k += 32)
            acc = fmaf(sx[k], __ldg(&wr[k]), acc);
#pragma unroll
        for (int o = 16; o; o >>= 1) acc += __shfl_down_sync(0xFFFFFFFFu, acc, o);
        if (lane == 0) Hr[(size_t)slot * DIM + j] = acc + __ldg(&b1[j]);
    }
}

// LN + head from exact h; patch L[row]. One block per slot.
__global__ __launch_bounds__(256)
void refine_fix(const float* __restrict__ Hr,
                const float* __restrict__ gamma, const float* __restrict__ beta,
                const float* __restrict__ W2, const float* __restrict__ b2,
                const int* __restrict__ rlist, const int* __restrict__ rcnt,
                float* __restrict__ L)
{
    const int slot = blockIdx.x;
    if (slot >= __ldg(rcnt)) return;
    const int t = threadIdx.x;
    const float4* h4 = (const float4*)(Hr + (size_t)slot * DIM);
    float4 v0 = h4[t*2];
    float4 v1 = h4[t*2+1];

    float s  = v0.x + v0.y + v0.z + v0.w + v1.x + v1.y + v1.z + v1.w;
    float ss = v0.x*v0.x + v0.y*v0.y + v0.z*v0.z + v0.w*v0.w
             + v1.x*v1.x + v1.y*v1.y + v1.z*v1.z + v1.w*v1.w;
    float2 red = block_reduce2(s, ss);
    const float inv_d = 1.f / (float)DIM;
    float mu = red.x * inv_d, var = red.y * inv_d - mu * mu;
    float rinv = rsqrtf(var + 1e-5f);

    const float4* g4  = (const float4*)gamma;
    const float4* be4 = (const float4*)beta;
    const float4* w04 = (const float4*)W2;
    const float4* w14 = (const float4*)(W2 + DIM);

    float l0 = 0.f, l1 = 0.f;
#pragma unroll
    for (int q = 0; q < 2; q++) {
        float4 v  = q ? v1 : v0;
        float4 g  = g4[t*2+q], be = be4[t*2+q], wa = w04[t*2+q], wbv = w14[t*2+q];
        float h;
        h = fmaxf(fmaf((v.x - mu)*rinv, g.x, be.x), 0.f); l0 += h*wa.x; l1 += h*wbv.x;
        h = fmaxf(fmaf((v.y - mu)*rinv, g.y, be.y), 0.f); l0 += h*wa.y; l1 += h*wbv.y;
        h = fmaxf(fmaf((v.z - mu)*rinv, g.z, be.z), 0.f); l0 += h*wa.z; l1 += h*wbv.z;
        h = fmaxf(fmaf((v.w - mu)*rinv, g.w, be.w), 0.f); l0 += h*wa.w; l1 += h*wbv.w;
    }
    float2 lr = block_reduce2(l0, l1);
    if (t == 0) {
        const int row = __ldg(&rlist[slot]);
        L[row*2]   = lr.x + __ldg(&b2[0]);
        L[row*2+1] = lr.y + __ldg(&b2[1]);
    }
}

// ---------------------------------------------------------------------------
// Deterministic route compaction: 1 block, 1024 threads, 32 rows each.
// ---------------------------------------------------------------------------
__global__ __launch_bounds__(1024)
void route_scan(const float* __restrict__ L0, int* __restrict__ fake_idx,
                int* __restrict__ real_idx, int* __restrict__ cnts)
{
    __shared__ int sf[1024];
    const int t = threadIdx.x;
    uint32_t mask = 0;
    int c = 0;
#pragma unroll
    for (int j = 0; j < 32; j++) {
        const int b = t * 32 + j;
        float2 f = ((const float2*)L0)[b];
        const bool fake = (f.x >= f.y);
        mask |= (uint32_t)fake << j;
        c += fake;
    }
    sf[t] = c;
    __syncthreads();
    for (int off = 1; off < 1024; off <<= 1) {
        int v = (t >= off) ? sf[t - off] : 0;
        __syncthreads();
        sf[t] += v;
        __syncthreads();
    }
    const int total_fake = sf[1023];
    const int excl = sf[t] - c;
    int fpos = excl;
#pragma unroll
    for (int j = 0; j < 32; j++) {
        const int b = t * 32 + j;
        if ((mask >> j) & 1) {
            fake_idx[fpos++] = b;
        } else {
            const int fake_before = excl + __popc(mask & ((1u << j) - 1u));
            real_idx[b - fake_before] = b;
        }
    }
    if (t == 0) { cnts[0] = total_fake; cnts[1] = BATCH - total_fake; }
}

// ---------------------------------------------------------------------------
extern "C" void kernel_launch(void* const* d_in, const int* in_sizes, int n_in,
                              void* d_out, int out_size)
{
    (void)in_sizes; (void)n_in; (void)out_size;
    const float* x = (const float*)d_in[0];

    float *H = nullptr, *L = nullptr, *Hr = nullptr;
    __nv_bfloat16 *xs = nullptr, *ws = nullptr;
    int *idx = nullptr, *cnt = nullptr;
    int *rl1 = nullptr, *rc1 = nullptr, *rl2 = nullptr, *rc2 = nullptr;
    cudaGetSymbolAddress((void**)&H,   g_H);
    cudaGetSymbolAddress((void**)&L,   g_logits);
    cudaGetSymbolAddress((void**)&Hr,  g_Hr);
    cudaGetSymbolAddress((void**)&xs,  g_xs);
    cudaGetSymbolAddress((void**)&ws,  g_ws);
    cudaGetSymbolAddress((void**)&idx, g_idx);
    cudaGetSymbolAddress((void**)&cnt, g_cnt);
    cudaGetSymbolAddress((void**)&rl1, g_rlist1);
    cudaGetSymbolAddress((void**)&rc1, g_rcnt1);
    cudaGetSymbolAddress((void**)&rl2, g_rlist2);
    cudaGetSymbolAddress((void**)&rc2, g_rcnt2);

    const size_t XN = (size_t)BATCH * DIM;
    const size_t WN = (size_t)DIM * DIM;
    __nv_bfloat16 *xh = xs, *xm = xs + XN;
    __nv_bfloat16 *wh = ws, *wm = ws + WN;

    constexpr int SMEM1 = NSTG * 16384;   // 96 KB (1-product kernel)
    constexpr int SMEM3 = NSF  * 32768;   // 96 KB (fused 3-product kernel)
    cudaFuncSetAttribute(gemm_mma1,       cudaFuncAttributeMaxDynamicSharedMemorySize, SMEM1);
    cudaFuncSetAttribute(gemm_mma3f<true>, cudaFuncAttributeMaxDynamicSharedMemorySize, SMEM3);

    split2_kernel<<<(int)(XN / 4 / 256), 256>>>(x, xh, xm, XN);

    dim3 grid(DIM / 128, BATCH / 128);        // (16, 256)
    dim3 grid_t1(DIM / 128, RCAP1 / 128);     // (16, 64)

    // ---- first (routing) branch: 1-product GEMM + tiered refine ----
    {
        const float* W1 = (const float*)d_in[1];
        const float* b1 = (const float*)d_in[2];
        const float* lg = (const float*)d_in[3];
        const float* lb = (const float*)d_in[4];
        const float* W2 = (const float*)d_in[5];
        const float* b2 = (const float*)d_in[6];
        split2_kernel<<<(int)(WN / 4 / 256), 256>>>(W1, wh, wm, WN);

        // tier-0: 1-product (hi*hi) full-batch GEMM
        gemm_mma1<<<grid, 256, SMEM1>>>(xh, wh, b1, H);
        ln_head8<false><<<BATCH / 8, 256>>>(H, lg, lb, W2, b2, nullptr, nullptr, L);

        // tier-1: |gap| < 2e-2 -> fused 3-product recompute, patch L
        flag_scan<<<1, 1024>>>(L, 2e-2f, RCAP1, rl1, rc1);
        gemm_mma3f<true><<<grid_t1, 256, SMEM3>>>(xh, xm, wh, wm, b1, H, rl1, rc1);
        ln_head8<true><<<RCAP1 / 8, 256>>>(H, lg, lb, W2, b2, rl1, rc1, L);

        // tier-2: |gap| < 1e-3 -> exact fp32 recompute, patch L
        flag_scan<<<1, 1024>>>(L, 1e-3f, RCAP2, rl2, rc2);
        refine_h<<<dim3(32, RCAP2), 256>>>(x, W1, b1, rl2, rc2, Hr);
        refine_fix<<<RCAP2, 256>>>(Hr, lg, lb, W2, b2, rl2, rc2, L);
    }

    route_scan<<<1, 1024>>>(L, idx, idx + BATCH, cnt);

    // ---- fake (route==0) and real branches: fused 3-product, gathered ----
    for (int br = 1; br < 3; br++) {
        const float* W1 = (const float*)d_in[1 + br * 6 + 0];
        const float* b1 = (const float*)d_in[1 + br * 6 + 1];
        const float* lg = (const float*)d_in[1 + br * 6 + 2];
        const float* lb = (const float*)d_in[1 + br * 6 + 3];
        const float* W2 = (const float*)d_in[1 + br * 6 + 4];
        const float* b2 = (const float*)d_in[1 + br * 6 + 5];

        split2_kernel<<<(int)(WN / 4 / 256), 256>>>(W1, wh, wm, WN);

        int* bidx = idx + (br - 1) * BATCH;
        int* bcnt = cnt + (br - 1);
        gemm_mma3f<true><<<grid, 256, SMEM3>>>(xh, xm, wh, wm, b1, H, bidx, bcnt);
        ln_head8<true><<<BATCH / 8, 256>>>(H, lg, lb, W2, b2, bidx, bcnt,
                                           (float*)d_out);
    }
}